// round 4
// baseline (speedup 1.0000x reference)
#include <cuda_runtime.h>
#include <cuda_bf16.h>
#include <cstdint>
#include <cstddef>

// ---------------------------------------------------------------------------
// Fixed shapes: D=128 (K2=64 bf16 pairs), A=64
// ---------------------------------------------------------------------------
static constexpr size_t MAXN = 200000;
static constexpr size_t MAXB = 256;

// Scratch (device globals; no runtime allocation allowed)
__device__ float    g_Xs  [MAXN * 64];     // hidden @ Ws^T
__device__ float    g_agg [MAXN * 128];    // segment sum
__device__ float    g_PR  [128 * 64];      // rel_emb @ Wr^T   (R<=128)
__device__ float    g_PQb [MAXB * 64];     // rel_emb[q_rel[b]] @ Wqr^T + b_qr
__device__ float    g_Wrt [128 * 64];      // Wr  transposed fp32 (for k_prep)
__device__ float    g_Wqrt[128 * 64];      // Wqr transposed fp32
// bf16-split weights, k2-major pairs: entry [k2][c] = {W[c][2k2], W[c][2k2+1]}
__device__ uint32_t g_WsH [64 * 64],  g_WsL [64 * 64];
__device__ uint32_t g_WhH [64 * 128], g_WhL [64 * 128];
__device__ uint32_t g_WihH[64 * 384], g_WihL[64 * 384];
__device__ int      g_h0nz;

// ---------------------------------------------------------------------------
// Helpers
// ---------------------------------------------------------------------------
__device__ __forceinline__ uint32_t pack_bf2(__nv_bfloat16 a, __nv_bfloat16 b)
{
    __nv_bfloat162 h; h.x = a; h.y = b;
    return *reinterpret_cast<uint32_t*>(&h);
}

__device__ __forceinline__ void split2(float x, float y, uint32_t& hi, uint32_t& lo)
{
    __nv_bfloat16 hx = __float2bfloat16_rn(x), hy = __float2bfloat16_rn(y);
    float rx = x - __bfloat162float(hx);
    float ry = y - __bfloat162float(hy);
    hi = pack_bf2(hx, hy);
    lo = pack_bf2(__float2bfloat16_rn(rx), __float2bfloat16_rn(ry));
}

__device__ __forceinline__ void mma_bf16(float* c, uint32_t a0, uint32_t a1,
                                         uint32_t a2, uint32_t a3,
                                         uint32_t b0, uint32_t b1)
{
    asm volatile(
        "mma.sync.aligned.m16n8k16.row.col.f32.bf16.bf16.f32 "
        "{%0,%1,%2,%3}, {%4,%5,%6,%7}, {%8,%9}, {%0,%1,%2,%3};\n"
        : "+f"(c[0]), "+f"(c[1]), "+f"(c[2]), "+f"(c[3])
        : "r"(a0), "r"(a1), "r"(a2), "r"(a3), "r"(b0), "r"(b1));
}

__device__ __forceinline__ float sigm(float x) { return 1.f / (1.f + __expf(-x)); }

// ---------------------------------------------------------------------------
// Tiny setup kernels
// ---------------------------------------------------------------------------
__global__ void k_flag0(int* flag) { *flag = 0; }

__global__ void k_zero_scan(float* agg, const float* __restrict__ h0, int nquads, int* flag)
{
    int i = blockIdx.x * blockDim.x + threadIdx.x;
    int stride = gridDim.x * blockDim.x;
    bool nz = false;
    float4 z = make_float4(0.f, 0.f, 0.f, 0.f);
    for (; i < nquads; i += stride) {
        reinterpret_cast<float4*>(agg)[i] = z;
        float4 v = reinterpret_cast<const float4*>(h0)[i];
        nz |= (v.x != 0.f) | (v.y != 0.f) | (v.z != 0.f) | (v.w != 0.f);
    }
    if (nz) atomicOr(flag, 1);
}

__global__ void k_transpose(const float* __restrict__ in, float* __restrict__ out,
                            int rows, int cols)
{
    int i = blockIdx.x * blockDim.x + threadIdx.x;
    if (i < rows * cols) {
        int r = i / cols, c = i % cols;
        out[(size_t)c * rows + r] = in[(size_t)r * cols + c];
    }
}

// Split W[rows][128] (fp32, row-major) into k2-major bf16-pair hi/lo [64][rows]
__global__ void k_prep_w(const float* __restrict__ W, uint32_t* __restrict__ hi,
                         uint32_t* __restrict__ lo, int rows)
{
    int i = blockIdx.x * blockDim.x + threadIdx.x;
    if (i >= 64 * rows) return;
    int k2 = i / rows, c = i % rows;
    float x = W[(size_t)c * 128 + 2 * k2];
    float y = W[(size_t)c * 128 + 2 * k2 + 1];
    uint32_t h, l;
    split2(x, y, h, l);
    hi[(size_t)k2 * rows + c] = h;
    lo[(size_t)k2 * rows + c] = l;
}

// PR[r][a] = dot(rel_emb[r], Wr[a]);  PQb[b][a] = dot(rel_emb[q_rel[b]], Wqr[a]) + b_qr[a]
__global__ void k_prep(const float* __restrict__ rel_emb,
                       const float* __restrict__ b_qr,
                       const int*   __restrict__ q_rel,
                       const float* __restrict__ Wrt,   // [128][64] fp32
                       const float* __restrict__ Wqrt,  // [128][64] fp32
                       float* __restrict__ PR, float* __restrict__ PQb,
                       int Rv, int Bv)
{
    __shared__ float se[128];
    int blk = blockIdx.x;
    int a = threadIdx.x;   // 0..63
    int r;
    const float* Wt;
    float* dst;
    float bias;
    if (blk < Rv) { r = blk;               Wt = Wrt;  dst = PR  + (size_t)blk * 64;        bias = 0.f; }
    else          { int b = blk - Rv; r = q_rel[b]; Wt = Wqrt; dst = PQb + (size_t)b * 64; bias = b_qr[a]; }
    se[a]      = rel_emb[(size_t)r * 128 + a];
    se[a + 64] = rel_emb[(size_t)r * 128 + a + 64];
    __syncthreads();
    float acc = bias;
    #pragma unroll 8
    for (int k = 0; k < 128; k++) acc += se[k] * Wt[k * 64 + a];
    dst[a] = acc;
}

// ---------------------------------------------------------------------------
// Tensor-core GEMM (3-term bf16 split) for Xs = hidden @ Ws^T  [N,64]
// BM=64, 256 threads, 8 warps: warp (w&3) -> 16-row tile, (w>>2) -> BN/2 cols.
// ---------------------------------------------------------------------------
template<int BN>
__global__ void k_gemm_mma(const float* __restrict__ A,
                           const uint32_t* __restrict__ Bhi,
                           const uint32_t* __restrict__ Blo,
                           float* __restrict__ C,
                           int M, int ldw, int ldc)
{
    constexpr int AP = 72;
    constexpr int BP = BN + 8;
    extern __shared__ uint32_t sm[];
    uint32_t* sAh = sm;                       // [64][AP]
    uint32_t* sAl = sAh + 64 * AP;
    uint32_t* sBh = sAl + 64 * AP;            // [64][BP]
    uint32_t* sBl = sBh + 64 * BP;

    const int t    = threadIdx.x;
    const int m0   = blockIdx.x * 64;
    const int col0 = blockIdx.y * BN;

    #pragma unroll
    for (int i = 0; i < 16; i++) {
        int f = t + i * 256;
        int row = f >> 6, k2 = f & 63;
        float2 v = (m0 + row < M)
                 ? reinterpret_cast<const float2*>(A)[(size_t)(m0 + row) * 64 + k2]
                 : make_float2(0.f, 0.f);
        uint32_t h, l;
        split2(v.x, v.y, h, l);
        sAh[row * AP + k2] = h;
        sAl[row * AP + k2] = l;
    }
    for (int f = t; f < 64 * BN; f += 256) {
        int k2 = f / BN, c = f % BN;
        sBh[k2 * BP + c] = Bhi[(size_t)k2 * ldw + col0 + c];
        sBl[k2 * BP + c] = Blo[(size_t)k2 * ldw + col0 + c];
    }
    __syncthreads();

    const int w = t >> 5, lane = t & 31;
    const int g = lane >> 2, tg = lane & 3;
    const int wm = (w & 3) * 16;
    const int wn = (w >> 2) * (BN / 2);
    constexpr int NT = BN / 16;

    float acc[NT][4];
    #pragma unroll
    for (int n = 0; n < NT; n++)
        #pragma unroll
        for (int j = 0; j < 4; j++) acc[n][j] = 0.f;

    #pragma unroll
    for (int kk = 0; kk < 64; kk += 8) {
        uint32_t ah0 = sAh[(wm + g)     * AP + kk + tg];
        uint32_t ah1 = sAh[(wm + g + 8) * AP + kk + tg];
        uint32_t ah2 = sAh[(wm + g)     * AP + kk + tg + 4];
        uint32_t ah3 = sAh[(wm + g + 8) * AP + kk + tg + 4];
        uint32_t al0 = sAl[(wm + g)     * AP + kk + tg];
        uint32_t al1 = sAl[(wm + g + 8) * AP + kk + tg];
        uint32_t al2 = sAl[(wm + g)     * AP + kk + tg + 4];
        uint32_t al3 = sAl[(wm + g + 8) * AP + kk + tg + 4];
        #pragma unroll
        for (int n = 0; n < NT; n++) {
            int nc = wn + n * 8 + g;
            uint32_t bh0 = sBh[(kk + tg)     * BP + nc];
            uint32_t bh1 = sBh[(kk + tg + 4) * BP + nc];
            uint32_t bl0 = sBl[(kk + tg)     * BP + nc];
            uint32_t bl1 = sBl[(kk + tg + 4) * BP + nc];
            mma_bf16(acc[n], ah0, ah1, ah2, ah3, bh0, bh1);
            mma_bf16(acc[n], ah0, ah1, ah2, ah3, bl0, bl1);
            mma_bf16(acc[n], al0, al1, al2, al3, bh0, bh1);
        }
    }

    const int row = m0 + wm + g;
    #pragma unroll
    for (int n = 0; n < NT; n++) {
        int cabs = col0 + wn + n * 8 + 2 * tg;
        if (row < M)
            *reinterpret_cast<float2*>(&C[(size_t)row * ldc + cabs]) =
                make_float2(acc[n][0], acc[n][1]);
        if (row + 8 < M)
            *reinterpret_cast<float2*>(&C[(size_t)(row + 8) * ldc + cabs]) =
                make_float2(acc[n][2], acc[n][3]);
    }
}

// ---------------------------------------------------------------------------
// FUSED: h_new = relu(agg@W_h^T); gi = h_new@W_ih^T + b_ih; GRU; score.
// Per 64-row tile: agg staged+split in smem -> mma -> hnew re-split IN PLACE
// (reusing A buffers) -> 3 W_ih chunks (reusing B buffers), 96 acc regs ->
// GRU + W_final dot in-register -> shfl+smem reduce -> 64 scores.
// Eliminates hnew & gi global buffers entirely (~820MB round-trip).
// ---------------------------------------------------------------------------
__global__ void __launch_bounds__(256, 1) k_fused(
    const float* __restrict__ agg,
    const uint32_t* __restrict__ WhH,  const uint32_t* __restrict__ WhL,
    const uint32_t* __restrict__ WihH, const uint32_t* __restrict__ WihL,
    const float* __restrict__ b_ih, const float* __restrict__ b_hh,
    const float* __restrict__ W_hh, const float* __restrict__ h0,
    const float* __restrict__ W_final, const int* __restrict__ flag,
    float* __restrict__ out, int M)
{
    constexpr int AP = 72, BP = 136, NT = 8;
    extern __shared__ uint32_t sm[];
    uint32_t* sAh = sm;                        // [64][AP]  agg, then hnew
    uint32_t* sAl = sAh + 64 * AP;
    uint32_t* sBh = sAl + 64 * AP;             // [64][BP]  Wh, then Wih chunks
    uint32_t* sBl = sBh + 64 * BP;
    float*    sSc = reinterpret_cast<float*>(sBl + 64 * BP);   // [64][2]

    const int t  = threadIdx.x;
    const int m0 = blockIdx.x * 64;
    const int w = t >> 5, lane = t & 31;
    const int g = lane >> 2, tg = lane & 3;
    const int wm = (w & 3) * 16;
    const int wn = (w >> 2) * 64;

    // stage + split agg
    #pragma unroll
    for (int i = 0; i < 16; i++) {
        int f = t + i * 256;
        int row = f >> 6, k2 = f & 63;
        float2 v = (m0 + row < M)
                 ? reinterpret_cast<const float2*>(agg)[(size_t)(m0 + row) * 64 + k2]
                 : make_float2(0.f, 0.f);
        uint32_t h, l;
        split2(v.x, v.y, h, l);
        sAh[row * AP + k2] = h;
        sAl[row * AP + k2] = l;
    }
    // stage W_h
    #pragma unroll
    for (int i = 0; i < 32; i++) {
        int f = t + i * 256;
        int k2 = f >> 7, c = f & 127;
        sBh[k2 * BP + c] = WhH[(size_t)k2 * 128 + c];
        sBl[k2 * BP + c] = WhL[(size_t)k2 * 128 + c];
    }
    __syncthreads();

    // ---- GEMM 1: h_new (pre-relu) ----
    float accH[NT][4];
    #pragma unroll
    for (int n = 0; n < NT; n++)
        #pragma unroll
        for (int j = 0; j < 4; j++) accH[n][j] = 0.f;

    #pragma unroll
    for (int kk = 0; kk < 64; kk += 8) {
        uint32_t ah0 = sAh[(wm + g)     * AP + kk + tg];
        uint32_t ah1 = sAh[(wm + g + 8) * AP + kk + tg];
        uint32_t ah2 = sAh[(wm + g)     * AP + kk + tg + 4];
        uint32_t ah3 = sAh[(wm + g + 8) * AP + kk + tg + 4];
        uint32_t al0 = sAl[(wm + g)     * AP + kk + tg];
        uint32_t al1 = sAl[(wm + g + 8) * AP + kk + tg];
        uint32_t al2 = sAl[(wm + g)     * AP + kk + tg + 4];
        uint32_t al3 = sAl[(wm + g + 8) * AP + kk + tg + 4];
        #pragma unroll
        for (int n = 0; n < NT; n++) {
            int nc = wn + n * 8 + g;
            uint32_t bh0 = sBh[(kk + tg)     * BP + nc];
            uint32_t bh1 = sBh[(kk + tg + 4) * BP + nc];
            uint32_t bl0 = sBl[(kk + tg)     * BP + nc];
            uint32_t bl1 = sBl[(kk + tg + 4) * BP + nc];
            mma_bf16(accH[n], ah0, ah1, ah2, ah3, bh0, bh1);
            mma_bf16(accH[n], ah0, ah1, ah2, ah3, bl0, bl1);
            mma_bf16(accH[n], al0, al1, al2, al3, bh0, bh1);
        }
    }
    __syncthreads();   // everyone done reading agg/Wh tiles

    // relu + split hnew back into the A buffers (same [row][k2] layout)
    #pragma unroll
    for (int n = 0; n < NT; n++) {
        int k2 = (wn + n * 8) / 2 + tg;        // this thread's col pair
        float v0 = fmaxf(accH[n][0], 0.f), v1 = fmaxf(accH[n][1], 0.f);
        float v2 = fmaxf(accH[n][2], 0.f), v3 = fmaxf(accH[n][3], 0.f);
        uint32_t h, l;
        split2(v0, v1, h, l);
        sAh[(wm + g) * AP + k2] = h;  sAl[(wm + g) * AP + k2] = l;
        split2(v2, v3, h, l);
        sAh[(wm + g + 8) * AP + k2] = h;  sAl[(wm + g + 8) * AP + k2] = l;
    }
    __syncthreads();

    // ---- GEMM 2: gi = hnew @ W_ih^T, three 128-col chunks, acc in regs ----
    float acc[3][NT][4];
    #pragma unroll
    for (int c3 = 0; c3 < 3; c3++)
        #pragma unroll
        for (int n = 0; n < NT; n++)
            #pragma unroll
            for (int j = 0; j < 4; j++) acc[c3][n][j] = 0.f;

    #pragma unroll
    for (int c3 = 0; c3 < 3; c3++) {
        #pragma unroll
        for (int i = 0; i < 32; i++) {
            int f = t + i * 256;
            int k2 = f >> 7, c = f & 127;
            sBh[k2 * BP + c] = WihH[(size_t)k2 * 384 + c3 * 128 + c];
            sBl[k2 * BP + c] = WihL[(size_t)k2 * 384 + c3 * 128 + c];
        }
        __syncthreads();
        #pragma unroll
        for (int kk = 0; kk < 64; kk += 8) {
            uint32_t ah0 = sAh[(wm + g)     * AP + kk + tg];
            uint32_t ah1 = sAh[(wm + g + 8) * AP + kk + tg];
            uint32_t ah2 = sAh[(wm + g)     * AP + kk + tg + 4];
            uint32_t ah3 = sAh[(wm + g + 8) * AP + kk + tg + 4];
            uint32_t al0 = sAl[(wm + g)     * AP + kk + tg];
            uint32_t al1 = sAl[(wm + g + 8) * AP + kk + tg];
            uint32_t al2 = sAl[(wm + g)     * AP + kk + tg + 4];
            uint32_t al3 = sAl[(wm + g + 8) * AP + kk + tg + 4];
            #pragma unroll
            for (int n = 0; n < NT; n++) {
                int nc = wn + n * 8 + g;
                uint32_t bh0 = sBh[(kk + tg)     * BP + nc];
                uint32_t bh1 = sBh[(kk + tg + 4) * BP + nc];
                uint32_t bl0 = sBl[(kk + tg)     * BP + nc];
                uint32_t bl1 = sBl[(kk + tg + 4) * BP + nc];
                mma_bf16(acc[c3][n], ah0, ah1, ah2, ah3, bh0, bh1);
                mma_bf16(acc[c3][n], ah0, ah1, ah2, ah3, bl0, bl1);
                mma_bf16(acc[c3][n], al0, al1, al2, al3, bh0, bh1);
            }
        }
        __syncthreads();
    }

    // ---- GRU + final score (in-register) ----
    const int nz = *flag;
    float p0 = 0.f, p1 = 0.f;
    #pragma unroll
    for (int n = 0; n < NT; n++) {
        #pragma unroll
        for (int jj = 0; jj < 2; jj++) {
            int cj = wn + n * 8 + 2 * tg + jj;
            float wf  = W_final[cj];
            float bir = b_ih[cj], biz = b_ih[128 + cj], bin = b_ih[256 + cj];
            float bhr = b_hh[cj], bhz = b_hh[128 + cj], bhn = b_hh[256 + cj];
            #pragma unroll
            for (int half = 0; half < 2; half++) {
                int grow = m0 + wm + g + half * 8;
                float hr = bhr, hz = bhz, hn = bhn, h0v = 0.f;
                if (nz && grow < M) {          // slow path (h0 != 0), rare
                    h0v = h0[(size_t)grow * 128 + cj];
                    float dr = 0.f, dz = 0.f, dn = 0.f;
                    for (int k = 0; k < 128; k++) {
                        float hv = h0[(size_t)grow * 128 + k];
                        dr += W_hh[(size_t)cj * 128 + k] * hv;
                        dz += W_hh[(size_t)(128 + cj) * 128 + k] * hv;
                        dn += W_hh[(size_t)(256 + cj) * 128 + k] * hv;
                    }
                    hr += dr; hz += dz; hn += dn;
                }
                float rg = sigm(acc[0][n][half * 2 + jj] + bir + hr);
                float zg = sigm(acc[1][n][half * 2 + jj] + biz + hz);
                float ng = tanhf(acc[2][n][half * 2 + jj] + bin + rg * hn);
                float h  = (1.f - zg) * ng + zg * h0v;
                if (half == 0) p0 += h * wf; else p1 += h * wf;
            }
        }
    }
    // reduce over tg (lanes g*4+tg are consecutive)
    p0 += __shfl_xor_sync(0xffffffffu, p0, 1);
    p0 += __shfl_xor_sync(0xffffffffu, p0, 2);
    p1 += __shfl_xor_sync(0xffffffffu, p1, 1);
    p1 += __shfl_xor_sync(0xffffffffu, p1, 2);
    if (tg == 0) {
        sSc[(wm + g) * 2     + (w >> 2)] = p0;
        sSc[(wm + g + 8) * 2 + (w >> 2)] = p1;
    }
    __syncthreads();
    if (t < 64 && m0 + t < M)
        out[m0 + t] = sSc[t * 2] + sSc[t * 2 + 1];
}

// ---------------------------------------------------------------------------
// Edge kernel: one warp per edge (unchanged)
// ---------------------------------------------------------------------------
__global__ void k_edge(const float* __restrict__ hidden, const float* __restrict__ rel_emb,
                       const float* __restrict__ w_alpha, const float* __restrict__ b_alpha,
                       const int* __restrict__ sub, const int* __restrict__ rel,
                       const int* __restrict__ obj, const int* __restrict__ ebatch,
                       const float* __restrict__ Xs, const float* __restrict__ PR,
                       const float* __restrict__ PQb, float* __restrict__ agg, int E)
{
    int warp = (blockIdx.x * blockDim.x + threadIdx.x) >> 5;
    int lane = threadIdx.x & 31;
    if (warp >= E) return;
    int s = sub[warp], r = rel[warp], o = obj[warp], b = ebatch[warp];

    float att0 = Xs[(size_t)s * 64 + lane]      + PR[r * 64 + lane]      + PQb[b * 64 + lane];
    float att1 = Xs[(size_t)s * 64 + lane + 32] + PR[r * 64 + lane + 32] + PQb[b * 64 + lane + 32];
    att0 = fmaxf(att0, 0.f);
    att1 = fmaxf(att1, 0.f);
    float p = att0 * w_alpha[lane] + att1 * w_alpha[lane + 32];
    #pragma unroll
    for (int off = 16; off; off >>= 1) p += __shfl_xor_sync(0xffffffffu, p, off);
    float alpha = 1.f / (1.f + __expf(-(p + b_alpha[0])));

    float4 h  = reinterpret_cast<const float4*>(hidden  + (size_t)s * 128)[lane];
    float4 rr = reinterpret_cast<const float4*>(rel_emb + (size_t)r * 128)[lane];
    float4 m  = make_float4(alpha * (h.x + rr.x), alpha * (h.y + rr.y),
                            alpha * (h.z + rr.z), alpha * (h.w + rr.w));
    atomicAdd(reinterpret_cast<float4*>(agg + (size_t)o * 128) + lane, m);
}

// ---------------------------------------------------------------------------
// Launch
// ---------------------------------------------------------------------------
extern "C" void kernel_launch(void* const* d_in, const int* in_sizes, int n_in,
                              void* d_out, int out_size)
{
    const float* hidden  = (const float*)d_in[0];
    const float* rel_emb = (const float*)d_in[1];
    const float* Ws      = (const float*)d_in[2];
    const float* Wr      = (const float*)d_in[3];
    const float* Wqr     = (const float*)d_in[4];
    const float* b_qr    = (const float*)d_in[5];
    const float* w_alpha = (const float*)d_in[6];
    const float* b_alpha = (const float*)d_in[7];
    const float* W_h     = (const float*)d_in[8];
    const float* W_ih    = (const float*)d_in[9];
    const float* W_hh    = (const float*)d_in[10];
    const float* b_ih    = (const float*)d_in[11];
    const float* b_hh    = (const float*)d_in[12];
    const float* W_final = (const float*)d_in[13];
    const float* h0      = (const float*)d_in[14];
    const int*   sub     = (const int*)d_in[15];
    const int*   rel     = (const int*)d_in[16];
    const int*   obj     = (const int*)d_in[17];
    const int*   ebatch  = (const int*)d_in[18];
    const int*   q_rel   = (const int*)d_in[19];
    float*       out     = (float*)d_out;

    const int Nn = in_sizes[0] / 128;
    const int Rv = in_sizes[1] / 128;
    const int Ev = in_sizes[15];
    const int Bv = in_sizes[19];

    float *pXs, *pAgg, *pPR, *pPQb, *pWrt, *pWqrt;
    uint32_t *pWsH, *pWsL, *pWhH, *pWhL, *pWihH, *pWihL;
    int* pFlag;
    cudaGetSymbolAddress((void**)&pXs,   g_Xs);
    cudaGetSymbolAddress((void**)&pAgg,  g_agg);
    cudaGetSymbolAddress((void**)&pPR,   g_PR);
    cudaGetSymbolAddress((void**)&pPQb,  g_PQb);
    cudaGetSymbolAddress((void**)&pWrt,  g_Wrt);
    cudaGetSymbolAddress((void**)&pWqrt, g_Wqrt);
    cudaGetSymbolAddress((void**)&pWsH,  g_WsH);
    cudaGetSymbolAddress((void**)&pWsL,  g_WsL);
    cudaGetSymbolAddress((void**)&pWhH,  g_WhH);
    cudaGetSymbolAddress((void**)&pWhL,  g_WhL);
    cudaGetSymbolAddress((void**)&pWihH, g_WihH);
    cudaGetSymbolAddress((void**)&pWihL, g_WihL);
    cudaGetSymbolAddress((void**)&pFlag, g_h0nz);

    // dynamic smem sizes
    const int SM64 = (64 * 72 * 2 + 64 * 72 * 2) * (int)sizeof(uint32_t);          // 73.7 KB
    const int SMF  = (64 * 72 * 2 + 64 * 136 * 2) * (int)sizeof(uint32_t) + 512;   // 107 KB
    cudaFuncSetAttribute(k_gemm_mma<64>, cudaFuncAttributeMaxDynamicSharedMemorySize, SM64);
    cudaFuncSetAttribute(k_fused,        cudaFuncAttributeMaxDynamicSharedMemorySize, SMF);

    // 1) flag reset, zero agg + scan h0
    k_flag0<<<1, 1>>>(pFlag);
    k_zero_scan<<<2048, 256>>>(pAgg, h0, Nn * 32, pFlag);

    // 2) weight prep
    k_transpose<<<(64 * 128 + 255) / 256, 256>>>(Wr,  pWrt,  64, 128);
    k_transpose<<<(64 * 128 + 255) / 256, 256>>>(Wqr, pWqrt, 64, 128);
    k_prep_w<<<(64 * 64  + 255) / 256, 256>>>(Ws,   pWsH,  pWsL,  64);
    k_prep_w<<<(64 * 128 + 255) / 256, 256>>>(W_h,  pWhH,  pWhL,  128);
    k_prep_w<<<(64 * 384 + 255) / 256, 256>>>(W_ih, pWihH, pWihL, 384);

    // 3) PR / PQb precompute (fp32)
    k_prep<<<Rv + Bv, 64>>>(rel_emb, b_qr, q_rel, pWrt, pWqrt, pPR, pPQb, Rv, Bv);

    // 4) Xs = hidden @ Ws^T   [N,64]
    int mtiles = (Nn + 63) / 64;
    k_gemm_mma<64><<<dim3(mtiles, 1), 256, SM64>>>(hidden, pWsH, pWsL, pXs, Nn, 64, 64);

    // 5) edge message passing + segment sum
    k_edge<<<(Ev + 7) / 8, 256>>>(hidden, rel_emb, w_alpha, b_alpha,
                                  sub, rel, obj, ebatch, pXs, pPR, pPQb, pAgg, Ev);

    // 6) fused: W_h GEMM + W_ih GEMM + GRU + final score
    k_fused<<<mtiles, 256, SMF>>>(pAgg, pWhH, pWhL, pWihH, pWihL,
                                  b_ih, b_hh, W_hh, h0, W_final, pFlag, out, Nn);
}

// round 5
// speedup vs baseline: 1.2189x; 1.2189x over previous
#include <cuda_runtime.h>
#include <cuda_bf16.h>
#include <cstdint>
#include <cstddef>

// ---------------------------------------------------------------------------
// Fixed shapes: D=128 (K2=64 bf16 pairs), A=64
// ---------------------------------------------------------------------------
static constexpr size_t MAXN = 200000;
static constexpr size_t MAXB = 256;

// Scratch (device globals; no runtime allocation allowed)
__device__ float    g_Xs  [MAXN * 64];     // hidden @ Ws^T
__device__ float    g_agg [MAXN * 128];    // segment sum
__device__ float    g_hnew[MAXN * 128];    // relu(agg @ W_h^T)
__device__ float    g_PR  [128 * 64];      // rel_emb @ Wr^T   (R<=128)
__device__ float    g_PQb [MAXB * 64];     // rel_emb[q_rel[b]] @ Wqr^T + b_qr
// bf16-split weights, k2-major pairs: entry [k2][c] = {W[c][2k2], W[c][2k2+1]}
__device__ uint32_t g_WsH [64 * 64],  g_WsL [64 * 64];
__device__ uint32_t g_WhH [64 * 128], g_WhL [64 * 128];
__device__ uint32_t g_WihH[64 * 384], g_WihL[64 * 384];
__device__ int      g_h0nz;

// ---------------------------------------------------------------------------
// Helpers
// ---------------------------------------------------------------------------
__device__ __forceinline__ uint32_t pack_bf2(__nv_bfloat16 a, __nv_bfloat16 b)
{
    __nv_bfloat162 h; h.x = a; h.y = b;
    return *reinterpret_cast<uint32_t*>(&h);
}

__device__ __forceinline__ void split2(float x, float y, uint32_t& hi, uint32_t& lo)
{
    __nv_bfloat16 hx = __float2bfloat16_rn(x), hy = __float2bfloat16_rn(y);
    float rx = x - __bfloat162float(hx);
    float ry = y - __bfloat162float(hy);
    hi = pack_bf2(hx, hy);
    lo = pack_bf2(__float2bfloat16_rn(rx), __float2bfloat16_rn(ry));
}

__device__ __forceinline__ void mma_bf16(float* c, uint32_t a0, uint32_t a1,
                                         uint32_t a2, uint32_t a3,
                                         uint32_t b0, uint32_t b1)
{
    asm volatile(
        "mma.sync.aligned.m16n8k16.row.col.f32.bf16.bf16.f32 "
        "{%0,%1,%2,%3}, {%4,%5,%6,%7}, {%8,%9}, {%0,%1,%2,%3};\n"
        : "+f"(c[0]), "+f"(c[1]), "+f"(c[2]), "+f"(c[3])
        : "r"(a0), "r"(a1), "r"(a2), "r"(a3), "r"(b0), "r"(b1));
}

__device__ __forceinline__ float sigm(float x) { return 1.f / (1.f + __expf(-x)); }

// ---------------------------------------------------------------------------
// k_setup: all weight prep in ONE launch.
//   blocks [0,144):       bf16-split Ws, W_h, W_ih into k2-major hi/lo
//   blocks [144, 144+PB): PR/PQb rows (4 rows per block, 64 threads each)
//   block 0 thread 0:     flag = 0
// ---------------------------------------------------------------------------
__global__ void k_setup(const float* __restrict__ Ws, const float* __restrict__ W_h,
                        const float* __restrict__ W_ih,
                        const float* __restrict__ Wr, const float* __restrict__ Wqr,
                        const float* __restrict__ rel_emb,
                        const float* __restrict__ b_qr, const int* __restrict__ q_rel,
                        uint32_t* __restrict__ WsH, uint32_t* __restrict__ WsL,
                        uint32_t* __restrict__ WhH, uint32_t* __restrict__ WhL,
                        uint32_t* __restrict__ WihH, uint32_t* __restrict__ WihL,
                        float* __restrict__ PR, float* __restrict__ PQb,
                        int* __restrict__ flag, int Rv, int Bv)
{
    const int blk = blockIdx.x, t = threadIdx.x;
    if (blk == 0 && t == 0) *flag = 0;

    if (blk < 144) {                         // split jobs: 36864 elems total
        int gid = blk * 256 + t;
        const float* W; uint32_t *H, *L; int rows, idx;
        if (gid < 4096)        { W = Ws;   H = WsH;  L = WsL;  rows = 64;  idx = gid; }
        else if (gid < 12288)  { W = W_h;  H = WhH;  L = WhL;  rows = 128; idx = gid - 4096; }
        else                   { W = W_ih; H = WihH; L = WihL; rows = 384; idx = gid - 12288; }
        int k2 = idx / rows, c = idx % rows;
        uint32_t h, l;
        split2(W[(size_t)c * 128 + 2 * k2], W[(size_t)c * 128 + 2 * k2 + 1], h, l);
        H[(size_t)k2 * rows + c] = h;
        L[(size_t)k2 * rows + c] = l;
    } else {                                 // PR / PQb rows
        int rid = (blk - 144) * 4 + (t >> 6);
        int a = t & 63;
        if (rid < Rv + Bv) {
            const float* Wrow; const float* emb; float* dst; float bias;
            if (rid < Rv) { Wrow = Wr;  emb = rel_emb + (size_t)rid * 128;
                            dst = PR + (size_t)rid * 64;  bias = 0.f; }
            else          { int b = rid - Rv; int r = q_rel[b];
                            Wrow = Wqr; emb = rel_emb + (size_t)r * 128;
                            dst = PQb + (size_t)b * 64;   bias = b_qr[a]; }
            float acc = bias;
            const float* wr = Wrow + (size_t)a * 128;
            #pragma unroll 8
            for (int k = 0; k < 128; k++) acc += emb[k] * wr[k];
            dst[a] = acc;
        }
    }
}

// ---------------------------------------------------------------------------
// zero agg (float4) + zero out + scan h0 for nonzeros
// ---------------------------------------------------------------------------
__global__ void k_zero_scan(float* agg, const float* __restrict__ h0, int nquads,
                            float* outbuf, int nout, int* flag)
{
    int i = blockIdx.x * blockDim.x + threadIdx.x;
    int stride = gridDim.x * blockDim.x;
    bool nz = false;
    float4 z = make_float4(0.f, 0.f, 0.f, 0.f);
    for (int j = i; j < nquads; j += stride) {
        reinterpret_cast<float4*>(agg)[j] = z;
        float4 v = reinterpret_cast<const float4*>(h0)[j];
        nz |= (v.x != 0.f) | (v.y != 0.f) | (v.z != 0.f) | (v.w != 0.f);
    }
    for (int j = i; j < nout; j += stride) outbuf[j] = 0.f;
    if (nz) atomicOr(flag, 1);
}

// ---------------------------------------------------------------------------
// BM=128 tensor-core GEMM (3-term bf16 split), 512 threads / 16 warps.
// Warp (w&7) -> 16-row tile, (w>>3) -> BN/2 columns.
// ---------------------------------------------------------------------------
template<int BN, bool RELU>
__global__ void __launch_bounds__(512, 1) k_gemm2(
    const float* __restrict__ A, const uint32_t* __restrict__ Bhi,
    const uint32_t* __restrict__ Blo, float* __restrict__ C,
    int M, int ldw, int ldc)
{
    constexpr int AP = 72, BP = BN + 8;
    extern __shared__ uint32_t sm[];
    uint32_t* sAh = sm;                       // [128][AP]
    uint32_t* sAl = sAh + 128 * AP;
    uint32_t* sBh = sAl + 128 * AP;           // [64][BP]
    uint32_t* sBl = sBh + 64 * BP;

    const int t  = threadIdx.x;
    const int m0 = blockIdx.x * 128;

    #pragma unroll
    for (int i = 0; i < 16; i++) {            // 8192 k2-pairs of A
        int f = t + i * 512;
        int row = f >> 6, k2 = f & 63;
        float2 v = (m0 + row < M)
                 ? reinterpret_cast<const float2*>(A)[(size_t)(m0 + row) * 64 + k2]
                 : make_float2(0.f, 0.f);
        uint32_t h, l;
        split2(v.x, v.y, h, l);
        sAh[row * AP + k2] = h;
        sAl[row * AP + k2] = l;
    }
    constexpr int BIT = (64 * BN) / 512;
    #pragma unroll
    for (int i = 0; i < BIT; i++) {
        int f = t + i * 512;
        int k2 = f / BN, c = f % BN;
        sBh[k2 * BP + c] = Bhi[(size_t)k2 * ldw + c];
        sBl[k2 * BP + c] = Blo[(size_t)k2 * ldw + c];
    }
    __syncthreads();

    const int w = t >> 5, lane = t & 31;
    const int g = lane >> 2, tg = lane & 3;
    const int wm = (w & 7) * 16;
    const int wn = (w >> 3) * (BN / 2);
    constexpr int NT = BN / 16;

    float acc[NT][4];
    #pragma unroll
    for (int n = 0; n < NT; n++)
        #pragma unroll
        for (int j = 0; j < 4; j++) acc[n][j] = 0.f;

    #pragma unroll
    for (int kk = 0; kk < 64; kk += 8) {
        uint32_t ah0 = sAh[(wm + g)     * AP + kk + tg];
        uint32_t ah1 = sAh[(wm + g + 8) * AP + kk + tg];
        uint32_t ah2 = sAh[(wm + g)     * AP + kk + tg + 4];
        uint32_t ah3 = sAh[(wm + g + 8) * AP + kk + tg + 4];
        uint32_t al0 = sAl[(wm + g)     * AP + kk + tg];
        uint32_t al1 = sAl[(wm + g + 8) * AP + kk + tg];
        uint32_t al2 = sAl[(wm + g)     * AP + kk + tg + 4];
        uint32_t al3 = sAl[(wm + g + 8) * AP + kk + tg + 4];
        #pragma unroll
        for (int n = 0; n < NT; n++) {
            int nc = wn + n * 8 + g;
            uint32_t bh0 = sBh[(kk + tg)     * BP + nc];
            uint32_t bh1 = sBh[(kk + tg + 4) * BP + nc];
            uint32_t bl0 = sBl[(kk + tg)     * BP + nc];
            uint32_t bl1 = sBl[(kk + tg + 4) * BP + nc];
            mma_bf16(acc[n], ah0, ah1, ah2, ah3, bh0, bh1);
            mma_bf16(acc[n], ah0, ah1, ah2, ah3, bl0, bl1);
            mma_bf16(acc[n], al0, al1, al2, al3, bh0, bh1);
        }
    }

    const int row = m0 + wm + g;
    #pragma unroll
    for (int n = 0; n < NT; n++) {
        int cabs = wn + n * 8 + 2 * tg;
        float v0 = acc[n][0], v1 = acc[n][1], v2 = acc[n][2], v3 = acc[n][3];
        if (RELU) {
            v0 = fmaxf(v0, 0.f); v1 = fmaxf(v1, 0.f);
            v2 = fmaxf(v2, 0.f); v3 = fmaxf(v3, 0.f);
        }
        if (row < M)
            *reinterpret_cast<float2*>(&C[(size_t)row * ldc + cabs]) = make_float2(v0, v1);
        if (row + 8 < M)
            *reinterpret_cast<float2*>(&C[(size_t)(row + 8) * ldc + cabs]) = make_float2(v2, v3);
    }
}

// ---------------------------------------------------------------------------
// Edge kernel: one warp per edge (unchanged; launch #4 -> profiled by ncu)
// ---------------------------------------------------------------------------
__global__ void k_edge(const float* __restrict__ hidden, const float* __restrict__ rel_emb,
                       const float* __restrict__ w_alpha, const float* __restrict__ b_alpha,
                       const int* __restrict__ sub, const int* __restrict__ rel,
                       const int* __restrict__ obj, const int* __restrict__ ebatch,
                       const float* __restrict__ Xs, const float* __restrict__ PR,
                       const float* __restrict__ PQb, float* __restrict__ agg, int E)
{
    int warp = (blockIdx.x * blockDim.x + threadIdx.x) >> 5;
    int lane = threadIdx.x & 31;
    if (warp >= E) return;
    int s = sub[warp], r = rel[warp], o = obj[warp], b = ebatch[warp];

    float att0 = Xs[(size_t)s * 64 + lane]      + PR[r * 64 + lane]      + PQb[b * 64 + lane];
    float att1 = Xs[(size_t)s * 64 + lane + 32] + PR[r * 64 + lane + 32] + PQb[b * 64 + lane + 32];
    att0 = fmaxf(att0, 0.f);
    att1 = fmaxf(att1, 0.f);
    float p = att0 * w_alpha[lane] + att1 * w_alpha[lane + 32];
    #pragma unroll
    for (int off = 16; off; off >>= 1) p += __shfl_xor_sync(0xffffffffu, p, off);
    float alpha = 1.f / (1.f + __expf(-(p + b_alpha[0])));

    float4 h  = reinterpret_cast<const float4*>(hidden  + (size_t)s * 128)[lane];
    float4 rr = reinterpret_cast<const float4*>(rel_emb + (size_t)r * 128)[lane];
    float4 m  = make_float4(alpha * (h.x + rr.x), alpha * (h.y + rr.y),
                            alpha * (h.z + rr.z), alpha * (h.w + rr.w));
    atomicAdd(reinterpret_cast<float4*>(agg + (size_t)o * 128) + lane, m);
}

// ---------------------------------------------------------------------------
// Fused W_ih GEMM + GRU + score. BM=128, 512 threads.
// Grid (mtiles, 2): blockIdx.y = 64-column half; each block does 3 gate-GEMMs
// of BN=64 (acc regs 48) over its half, then GRU + partial score via atomicAdd
// into the pre-zeroed out buffer. gi global buffer eliminated.
// ---------------------------------------------------------------------------
__global__ void __launch_bounds__(512, 1) k_wihgru(
    const float* __restrict__ hnew,
    const uint32_t* __restrict__ WihH, const uint32_t* __restrict__ WihL,
    const float* __restrict__ b_ih, const float* __restrict__ b_hh,
    const float* __restrict__ W_hh, const float* __restrict__ h0,
    const float* __restrict__ W_final, const int* __restrict__ flag,
    float* __restrict__ out, int M)
{
    constexpr int AP = 72, BP = 72, NT = 4;
    extern __shared__ uint32_t sm[];
    uint32_t* sAh = sm;                        // [128][AP]
    uint32_t* sAl = sAh + 128 * AP;
    uint32_t* sBh = sAl + 128 * AP;            // [64][BP], reused per gate
    uint32_t* sBl = sBh + 64 * BP;
    float*    sSc = reinterpret_cast<float*>(sBl + 64 * BP);   // [128][2]

    const int t    = threadIdx.x;
    const int m0   = blockIdx.x * 128;
    const int half = blockIdx.y;               // 0 or 1 -> columns half*64..+63

    #pragma unroll
    for (int i = 0; i < 16; i++) {             // stage + split hnew tile
        int f = t + i * 512;
        int row = f >> 6, k2 = f & 63;
        float2 v = (m0 + row < M)
                 ? reinterpret_cast<const float2*>(hnew)[(size_t)(m0 + row) * 64 + k2]
                 : make_float2(0.f, 0.f);
        uint32_t h, l;
        split2(v.x, v.y, h, l);
        sAh[row * AP + k2] = h;
        sAl[row * AP + k2] = l;
    }

    const int w = t >> 5, lane = t & 31;
    const int g = lane >> 2, tg = lane & 3;
    const int wm = (w & 7) * 16;
    const int wn = (w >> 3) * 32;

    float acc[3][NT][4];
    #pragma unroll
    for (int c3 = 0; c3 < 3; c3++)
        #pragma unroll
        for (int n = 0; n < NT; n++)
            #pragma unroll
            for (int j = 0; j < 4; j++) acc[c3][n][j] = 0.f;

    #pragma unroll
    for (int gate = 0; gate < 3; gate++) {
        __syncthreads();                       // protect sB from previous gate readers
        #pragma unroll
        for (int i = 0; i < 8; i++) {          // 4096 u32 per buffer
            int f = t + i * 512;
            int k2 = f >> 6, c = f & 63;
            size_t src = (size_t)k2 * 384 + gate * 128 + half * 64 + c;
            sBh[k2 * BP + c] = WihH[src];
            sBl[k2 * BP + c] = WihL[src];
        }
        __syncthreads();
        #pragma unroll
        for (int kk = 0; kk < 64; kk += 8) {
            uint32_t ah0 = sAh[(wm + g)     * AP + kk + tg];
            uint32_t ah1 = sAh[(wm + g + 8) * AP + kk + tg];
            uint32_t ah2 = sAh[(wm + g)     * AP + kk + tg + 4];
            uint32_t ah3 = sAh[(wm + g + 8) * AP + kk + tg + 4];
            uint32_t al0 = sAl[(wm + g)     * AP + kk + tg];
            uint32_t al1 = sAl[(wm + g + 8) * AP + kk + tg];
            uint32_t al2 = sAl[(wm + g)     * AP + kk + tg + 4];
            uint32_t al3 = sAl[(wm + g + 8) * AP + kk + tg + 4];
            #pragma unroll
            for (int n = 0; n < NT; n++) {
                int nc = wn + n * 8 + g;
                uint32_t bh0 = sBh[(kk + tg)     * BP + nc];
                uint32_t bh1 = sBh[(kk + tg + 4) * BP + nc];
                uint32_t bl0 = sBl[(kk + tg)     * BP + nc];
                uint32_t bl1 = sBl[(kk + tg + 4) * BP + nc];
                mma_bf16(acc[gate][n], ah0, ah1, ah2, ah3, bh0, bh1);
                mma_bf16(acc[gate][n], ah0, ah1, ah2, ah3, bl0, bl1);
                mma_bf16(acc[gate][n], al0, al1, al2, al3, bh0, bh1);
            }
        }
    }

    // ---- GRU + partial score ----
    const int nz = *flag;
    float p0 = 0.f, p1 = 0.f;
    #pragma unroll
    for (int n = 0; n < NT; n++) {
        #pragma unroll
        for (int jj = 0; jj < 2; jj++) {
            int cabs = half * 64 + wn + n * 8 + 2 * tg + jj;   // 0..127
            float wf  = W_final[cabs];
            float bir = b_ih[cabs], biz = b_ih[128 + cabs], bin = b_ih[256 + cabs];
            float bhr = b_hh[cabs], bhz = b_hh[128 + cabs], bhn = b_hh[256 + cabs];
            #pragma unroll
            for (int hrw = 0; hrw < 2; hrw++) {
                int grow = m0 + wm + g + hrw * 8;
                float hr = bhr, hz = bhz, hn = bhn, h0v = 0.f;
                if (nz && grow < M) {          // slow path (h0 != 0), not taken here
                    h0v = h0[(size_t)grow * 128 + cabs];
                    float dr = 0.f, dz = 0.f, dn = 0.f;
                    for (int k = 0; k < 128; k++) {
                        float hv = h0[(size_t)grow * 128 + k];
                        dr += W_hh[(size_t)cabs * 128 + k] * hv;
                        dz += W_hh[(size_t)(128 + cabs) * 128 + k] * hv;
                        dn += W_hh[(size_t)(256 + cabs) * 128 + k] * hv;
                    }
                    hr += dr; hz += dz; hn += dn;
                }
                float rg = sigm(acc[0][n][hrw * 2 + jj] + bir + hr);
                float zg = sigm(acc[1][n][hrw * 2 + jj] + biz + hz);
                float ng = tanhf(acc[2][n][hrw * 2 + jj] + bin + rg * hn);
                float h  = (1.f - zg) * ng + zg * h0v;
                if (hrw == 0) p0 += h * wf; else p1 += h * wf;
            }
        }
    }
    p0 += __shfl_xor_sync(0xffffffffu, p0, 1);
    p0 += __shfl_xor_sync(0xffffffffu, p0, 2);
    p1 += __shfl_xor_sync(0xffffffffu, p1, 1);
    p1 += __shfl_xor_sync(0xffffffffu, p1, 2);
    if (tg == 0) {
        sSc[(wm + g) * 2     + (w >> 3)] = p0;
        sSc[(wm + g + 8) * 2 + (w >> 3)] = p1;
    }
    __syncthreads();
    if (t < 128 && m0 + t < M)
        atomicAdd(&out[m0 + t], sSc[t * 2] + sSc[t * 2 + 1]);
}

// ---------------------------------------------------------------------------
// Launch.  Order matters: k_edge is launch #4 (ncu capture slot).
// ---------------------------------------------------------------------------
extern "C" void kernel_launch(void* const* d_in, const int* in_sizes, int n_in,
                              void* d_out, int out_size)
{
    const float* hidden  = (const float*)d_in[0];
    const float* rel_emb = (const float*)d_in[1];
    const float* Ws      = (const float*)d_in[2];
    const float* Wr      = (const float*)d_in[3];
    const float* Wqr     = (const float*)d_in[4];
    const float* b_qr    = (const float*)d_in[5];
    const float* w_alpha = (const float*)d_in[6];
    const float* b_alpha = (const float*)d_in[7];
    const float* W_h     = (const float*)d_in[8];
    const float* W_ih    = (const float*)d_in[9];
    const float* W_hh    = (const float*)d_in[10];
    const float* b_ih    = (const float*)d_in[11];
    const float* b_hh    = (const float*)d_in[12];
    const float* W_final = (const float*)d_in[13];
    const float* h0      = (const float*)d_in[14];
    const int*   sub     = (const int*)d_in[15];
    const int*   rel     = (const int*)d_in[16];
    const int*   obj     = (const int*)d_in[17];
    const int*   ebatch  = (const int*)d_in[18];
    const int*   q_rel   = (const int*)d_in[19];
    float*       out     = (float*)d_out;

    const int Nn = in_sizes[0] / 128;
    const int Rv = in_sizes[1] / 128;
    const int Ev = in_sizes[15];
    const int Bv = in_sizes[19];

    float *pXs, *pAgg, *pHnew, *pPR, *pPQb;
    uint32_t *pWsH, *pWsL, *pWhH, *pWhL, *pWihH, *pWihL;
    int* pFlag;
    cudaGetSymbolAddress((void**)&pXs,   g_Xs);
    cudaGetSymbolAddress((void**)&pAgg,  g_agg);
    cudaGetSymbolAddress((void**)&pHnew, g_hnew);
    cudaGetSymbolAddress((void**)&pPR,   g_PR);
    cudaGetSymbolAddress((void**)&pPQb,  g_PQb);
    cudaGetSymbolAddress((void**)&pWsH,  g_WsH);
    cudaGetSymbolAddress((void**)&pWsL,  g_WsL);
    cudaGetSymbolAddress((void**)&pWhH,  g_WhH);
    cudaGetSymbolAddress((void**)&pWhL,  g_WhL);
    cudaGetSymbolAddress((void**)&pWihH, g_WihH);
    cudaGetSymbolAddress((void**)&pWihL, g_WihL);
    cudaGetSymbolAddress((void**)&pFlag, g_h0nz);

    // dynamic smem sizes
    const int SMX = (128 * 72 * 2 + 64 * 72 * 2)  * (int)sizeof(uint32_t);          // 108 KB
    const int SMW = (128 * 72 * 2 + 64 * 136 * 2) * (int)sizeof(uint32_t);          // 140 KB
    const int SMG = (128 * 72 * 2 + 64 * 72 * 2)  * (int)sizeof(uint32_t) + 1024;   // 109 KB
    cudaFuncSetAttribute(k_gemm2<64,  false>, cudaFuncAttributeMaxDynamicSharedMemorySize, SMX);
    cudaFuncSetAttribute(k_gemm2<128, true >, cudaFuncAttributeMaxDynamicSharedMemorySize, SMW);
    cudaFuncSetAttribute(k_wihgru,            cudaFuncAttributeMaxDynamicSharedMemorySize, SMG);

    const int mt128 = (Nn + 127) / 128;
    const int prepBlocks = 144 + (Rv + Bv + 3) / 4;

    // 1) all weight prep + PR/PQb + flag reset
    k_setup<<<prepBlocks, 256>>>(Ws, W_h, W_ih, Wr, Wqr, rel_emb, b_qr, q_rel,
                                 pWsH, pWsL, pWhH, pWhL, pWihH, pWihL,
                                 pPR, pPQb, pFlag, Rv, Bv);

    // 2) zero agg + zero out + scan h0
    k_zero_scan<<<2048, 256>>>(pAgg, h0, Nn * 32, out, out_size, pFlag);

    // 3) Xs = hidden @ Ws^T   [N,64]
    k_gemm2<64, false><<<mt128, 512, SMX>>>(hidden, pWsH, pWsL, pXs, Nn, 64, 64);

    // 4) edge message passing + segment sum   <-- ncu capture slot
    k_edge<<<(Ev + 7) / 8, 256>>>(hidden, rel_emb, w_alpha, b_alpha,
                                  sub, rel, obj, ebatch, pXs, pPR, pPQb, pAgg, Ev);

    // 5) h_new = relu(agg @ W_h^T)   [N,128]
    k_gemm2<128, true><<<mt128, 512, SMW>>>(pAgg, pWhH, pWhL, pHnew, Nn, 128, 128);

    // 6) fused W_ih GEMM + GRU + score
    k_wihgru<<<dim3(mt128, 2), 512, SMG>>>(pHnew, pWihH, pWihL, b_ih, b_hh,
                                           W_hh, h0, W_final, pFlag, out, Nn);
}

// round 6
// speedup vs baseline: 1.3859x; 1.1370x over previous
#include <cuda_runtime.h>
#include <cuda_bf16.h>
#include <cstdint>
#include <cstddef>

// ---------------------------------------------------------------------------
// Fixed shapes: D=128 (K2=64 bf16 pairs), A=64
// ---------------------------------------------------------------------------
static constexpr size_t MAXN = 200000;
static constexpr size_t MAXB = 256;

// Scratch (device globals; no runtime allocation allowed)
__device__ float    g_Xs  [MAXN * 64];     // hidden @ Ws^T
__device__ float    g_agg [MAXN * 128];    // segment sum
__device__ float    g_hnew[MAXN * 128];    // relu(agg @ W_h^T)
__device__ float    g_PR  [128 * 64];      // rel_emb @ Wr^T   (R<=128)
__device__ float    g_PQb [MAXB * 64];     // rel_emb[q_rel[b]] @ Wqr^T + b_qr
// bf16-split weights, c-major pairs: entry [c][k2] = {W[c][2k2], W[c][2k2+1]}
__device__ uint32_t g_WsH [64 * 64],  g_WsL [64 * 64];
__device__ uint32_t g_WhH [128 * 64], g_WhL [128 * 64];
__device__ uint32_t g_WihH[384 * 64], g_WihL[384 * 64];
__device__ int      g_h0nz;                // zero-initialized; reset by k_flagreset

// ---------------------------------------------------------------------------
// Helpers
// ---------------------------------------------------------------------------
__device__ __forceinline__ uint32_t pack_bf2(__nv_bfloat16 a, __nv_bfloat16 b)
{
    __nv_bfloat162 h; h.x = a; h.y = b;
    return *reinterpret_cast<uint32_t*>(&h);
}

__device__ __forceinline__ void split2(float x, float y, uint32_t& hi, uint32_t& lo)
{
    __nv_bfloat16 hx = __float2bfloat16_rn(x), hy = __float2bfloat16_rn(y);
    float rx = x - __bfloat162float(hx);
    float ry = y - __bfloat162float(hy);
    hi = pack_bf2(hx, hy);
    lo = pack_bf2(__float2bfloat16_rn(rx), __float2bfloat16_rn(ry));
}

__device__ __forceinline__ void mma_bf16(float* c, uint32_t a0, uint32_t a1,
                                         uint32_t a2, uint32_t a3,
                                         uint32_t b0, uint32_t b1)
{
    asm volatile(
        "mma.sync.aligned.m16n8k16.row.col.f32.bf16.bf16.f32 "
        "{%0,%1,%2,%3}, {%4,%5,%6,%7}, {%8,%9}, {%0,%1,%2,%3};\n"
        : "+f"(c[0]), "+f"(c[1]), "+f"(c[2]), "+f"(c[3])
        : "r"(a0), "r"(a1), "r"(a2), "r"(a3), "r"(b0), "r"(b1));
}

__device__ __forceinline__ void ldsm_x4(uint32_t& r0, uint32_t& r1, uint32_t& r2,
                                        uint32_t& r3, uint32_t addr)
{
    asm volatile("ldmatrix.sync.aligned.m8n8.x4.shared.b16 {%0,%1,%2,%3}, [%4];"
                 : "=r"(r0), "=r"(r1), "=r"(r2), "=r"(r3) : "r"(addr));
}

__device__ __forceinline__ uint32_t smem_u32(const void* p)
{
    uint32_t a;
    asm("{ .reg .u64 t; cvta.to.shared.u64 t, %1; cvt.u32.u64 %0, t; }"
        : "=r"(a) : "l"(p));
    return a;
}

__device__ __forceinline__ float sigm(float x) { return 1.f / (1.f + __expf(-x)); }

// ---------------------------------------------------------------------------
// k_setupzero: weight splits + PR/PQb + agg/out zero + h0 scan, one launch.
//   blocks [0,144):             bf16-split Ws/W_h/W_ih into c-major hi/lo
//   blocks [144, prepBlocks):   PR / PQb rows
//   blocks [prepBlocks, ...):   zero agg & out, scan h0 (atomicOr flag)
// flag is NOT reset here (k_flagreset does that at the tail of the sequence).
// ---------------------------------------------------------------------------
__global__ void k_setupzero(
    const float* __restrict__ Ws, const float* __restrict__ W_h,
    const float* __restrict__ W_ih,
    const float* __restrict__ Wr, const float* __restrict__ Wqr,
    const float* __restrict__ rel_emb,
    const float* __restrict__ b_qr, const int* __restrict__ q_rel,
    uint32_t* __restrict__ WsH, uint32_t* __restrict__ WsL,
    uint32_t* __restrict__ WhH, uint32_t* __restrict__ WhL,
    uint32_t* __restrict__ WihH, uint32_t* __restrict__ WihL,
    float* __restrict__ PR, float* __restrict__ PQb,
    float* __restrict__ agg, const float* __restrict__ h0, int nquads,
    float* __restrict__ outbuf, int nout,
    int* __restrict__ flag, int Rv, int Bv, int prepBlocks)
{
    const int blk = blockIdx.x, t = threadIdx.x;

    if (blk < 144) {                               // 36864 split elems
        int gid = blk * 256 + t;
        const float* W; uint32_t *H, *L; int idx;
        if (gid < 4096)       { W = Ws;   H = WsH;  L = WsL;  idx = gid; }
        else if (gid < 12288) { W = W_h;  H = WhH;  L = WhL;  idx = gid - 4096; }
        else                  { W = W_ih; H = WihH; L = WihL; idx = gid - 12288; }
        int c = idx >> 6, k2 = idx & 63;
        uint32_t h, l;
        split2(W[(size_t)c * 128 + 2 * k2], W[(size_t)c * 128 + 2 * k2 + 1], h, l);
        H[idx] = h;                                // c-major: [c][64]
        L[idx] = l;
    } else if (blk < prepBlocks) {                 // PR / PQb rows
        int rid = (blk - 144) * 4 + (t >> 6);
        int a = t & 63;
        if (rid < Rv + Bv) {
            const float* Wrow; const float* emb; float* dst; float bias;
            if (rid < Rv) { Wrow = Wr;  emb = rel_emb + (size_t)rid * 128;
                            dst = PR + (size_t)rid * 64;  bias = 0.f; }
            else          { int b = rid - Rv; int r = q_rel[b];
                            Wrow = Wqr; emb = rel_emb + (size_t)r * 128;
                            dst = PQb + (size_t)b * 64;   bias = b_qr[a]; }
            float acc = bias;
            const float* wr = Wrow + (size_t)a * 128;
            #pragma unroll 8
            for (int k = 0; k < 128; k++) acc += emb[k] * wr[k];
            dst[a] = acc;
        }
    } else {                                       // zero + scan
        int zb = gridDim.x - prepBlocks;
        int i = (blk - prepBlocks) * 256 + t;
        int stride = zb * 256;
        bool nz = false;
        float4 z = make_float4(0.f, 0.f, 0.f, 0.f);
        for (int j = i; j < nquads; j += stride) {
            reinterpret_cast<float4*>(agg)[j] = z;
            float4 v = reinterpret_cast<const float4*>(h0)[j];
            nz |= (v.x != 0.f) | (v.y != 0.f) | (v.z != 0.f) | (v.w != 0.f);
        }
        for (int j = i; j < nout; j += stride) outbuf[j] = 0.f;
        if (nz) atomicOr(flag, 1);
    }
}

// ---------------------------------------------------------------------------
// BM=128 tensor-core GEMM (3-term bf16 split), 512 threads / 16 warps,
// LDSM fragment loads. A: fp32 [M][128] split on the fly. B: pre-split
// c-major [BN][64] hi/lo. Smem strides padded to 68 u32 (conflict-free for
// both staging stores and ldmatrix phases).
// ---------------------------------------------------------------------------
template<int BN, bool RELU>
__global__ void __launch_bounds__(512, 1) k_gemm2(
    const float* __restrict__ A, const uint32_t* __restrict__ Bhi,
    const uint32_t* __restrict__ Blo, float* __restrict__ C,
    int M, int ldc)
{
    constexpr int AP = 68, BP = 68;
    constexpr int NPAIR = BN / 32;                 // ldmatrix.x4 B loads per buf
    extern __shared__ uint32_t sm[];
    uint32_t* sAh = sm;                            // [128][AP]
    uint32_t* sAl = sAh + 128 * AP;
    uint32_t* sBh = sAl + 128 * AP;                // [BN][BP]
    uint32_t* sBl = sBh + BN * BP;

    const int t  = threadIdx.x;
    const int m0 = blockIdx.x * 128;

    #pragma unroll
    for (int i = 0; i < 16; i++) {                 // stage + split A
        int f = t + i * 512;
        int row = f >> 6, k2 = f & 63;
        float2 v = (m0 + row < M)
                 ? reinterpret_cast<const float2*>(A)[(size_t)(m0 + row) * 64 + k2]
                 : make_float2(0.f, 0.f);
        uint32_t h, l;
        split2(v.x, v.y, h, l);
        sAh[row * AP + k2] = h;
        sAl[row * AP + k2] = l;
    }
    #pragma unroll
    for (int i = 0; i < (BN * 64) / 512; i++) {    // stage B (straight copy)
        int f = t + i * 512;
        sBh[(f >> 6) * BP + (f & 63)] = Bhi[f];
        sBl[(f >> 6) * BP + (f & 63)] = Blo[f];
    }
    __syncthreads();

    const int w = t >> 5, lane = t & 31;
    const int g = lane >> 2, tg = lane & 3;
    const int wm = (w & 7) * 16;
    const int wn = (w >> 3) * (BN / 2);

    // lane-dependent ldmatrix base addresses
    const uint32_t aRowOff = ((wm + (lane & 15)) * AP + (lane >> 4) * 4) << 2;
    const uint32_t aH = smem_u32(sAh) + aRowOff;
    const uint32_t aL = smem_u32(sAl) + aRowOff;
    uint32_t bH[NPAIR], bL[NPAIR];
    #pragma unroll
    for (int np = 0; np < NPAIR; np++) {
        uint32_t cb = wn + np * 16 + (lane & 7) + ((lane >> 4) << 3);
        uint32_t off = (cb * BP + ((lane >> 3) & 1) * 4) << 2;
        bH[np] = smem_u32(sBh) + off;
        bL[np] = smem_u32(sBl) + off;
    }

    float acc[BN / 16][4];
    #pragma unroll
    for (int n = 0; n < BN / 16; n++)
        #pragma unroll
        for (int j = 0; j < 4; j++) acc[n][j] = 0.f;

    #pragma unroll
    for (int kb = 0; kb < 8; kb++) {
        const uint32_t ko = kb * 32;               // 8 u32 = 32 bytes per k-step
        uint32_t ah0, ah1, ah2, ah3, al0, al1, al2, al3;
        ldsm_x4(ah0, ah1, ah2, ah3, aH + ko);
        ldsm_x4(al0, al1, al2, al3, aL + ko);
        #pragma unroll
        for (int np = 0; np < NPAIR; np++) {
            uint32_t bh0, bh1, bh2, bh3, bl0, bl1, bl2, bl3;
            ldsm_x4(bh0, bh1, bh2, bh3, bH[np] + ko);
            ldsm_x4(bl0, bl1, bl2, bl3, bL[np] + ko);
            mma_bf16(acc[2*np],   ah0, ah1, ah2, ah3, bh0, bh1);
            mma_bf16(acc[2*np],   ah0, ah1, ah2, ah3, bl0, bl1);
            mma_bf16(acc[2*np],   al0, al1, al2, al3, bh0, bh1);
            mma_bf16(acc[2*np+1], ah0, ah1, ah2, ah3, bh2, bh3);
            mma_bf16(acc[2*np+1], ah0, ah1, ah2, ah3, bl2, bl3);
            mma_bf16(acc[2*np+1], al0, al1, al2, al3, bh2, bh3);
        }
    }

    const int row = m0 + wm + g;
    #pragma unroll
    for (int n = 0; n < BN / 16; n++) {
        int cabs = wn + n * 8 + 2 * tg;
        float v0 = acc[n][0], v1 = acc[n][1], v2 = acc[n][2], v3 = acc[n][3];
        if (RELU) {
            v0 = fmaxf(v0, 0.f); v1 = fmaxf(v1, 0.f);
            v2 = fmaxf(v2, 0.f); v3 = fmaxf(v3, 0.f);
        }
        if (row < M)
            *reinterpret_cast<float2*>(&C[(size_t)row * ldc + cabs]) = make_float2(v0, v1);
        if (row + 8 < M)
            *reinterpret_cast<float2*>(&C[(size_t)(row + 8) * ldc + cabs]) = make_float2(v2, v3);
    }
}

// ---------------------------------------------------------------------------
// Edge kernel: one warp per edge
// ---------------------------------------------------------------------------
__global__ void k_edge(const float* __restrict__ hidden, const float* __restrict__ rel_emb,
                       const float* __restrict__ w_alpha, const float* __restrict__ b_alpha,
                       const int* __restrict__ sub, const int* __restrict__ rel,
                       const int* __restrict__ obj, const int* __restrict__ ebatch,
                       const float* __restrict__ Xs, const float* __restrict__ PR,
                       const float* __restrict__ PQb, float* __restrict__ agg, int E)
{
    int warp = (blockIdx.x * blockDim.x + threadIdx.x) >> 5;
    int lane = threadIdx.x & 31;
    if (warp >= E) return;
    int s = sub[warp], r = rel[warp], o = obj[warp], b = ebatch[warp];

    float att0 = Xs[(size_t)s * 64 + lane]      + PR[r * 64 + lane]      + PQb[b * 64 + lane];
    float att1 = Xs[(size_t)s * 64 + lane + 32] + PR[r * 64 + lane + 32] + PQb[b * 64 + lane + 32];
    att0 = fmaxf(att0, 0.f);
    att1 = fmaxf(att1, 0.f);
    float p = att0 * w_alpha[lane] + att1 * w_alpha[lane + 32];
    #pragma unroll
    for (int off = 16; off; off >>= 1) p += __shfl_xor_sync(0xffffffffu, p, off);
    float alpha = 1.f / (1.f + __expf(-(p + b_alpha[0])));

    float4 h  = reinterpret_cast<const float4*>(hidden  + (size_t)s * 128)[lane];
    float4 rr = reinterpret_cast<const float4*>(rel_emb + (size_t)r * 128)[lane];
    float4 m  = make_float4(alpha * (h.x + rr.x), alpha * (h.y + rr.y),
                            alpha * (h.z + rr.z), alpha * (h.w + rr.w));
    atomicAdd(reinterpret_cast<float4*>(agg + (size_t)o * 128) + lane, m);
}

// ---------------------------------------------------------------------------
// Fused W_ih GEMM + GRU + score (h0 == 0 fast path; k_fixup handles h0 != 0).
// BM=128, 512 threads, grid (mtiles, 2) column-halves. ALL 3 gate weight
// tiles staged up front (no inter-gate barriers). Partial scores combined
// via atomicAdd into pre-zeroed out.
// ---------------------------------------------------------------------------
__global__ void __launch_bounds__(512, 1) k_wihgru(
    const float* __restrict__ hnew,
    const uint32_t* __restrict__ WihH, const uint32_t* __restrict__ WihL,
    const float* __restrict__ b_ih, const float* __restrict__ b_hh,
    const float* __restrict__ W_final, float* __restrict__ out, int M)
{
    constexpr int AP = 68, BP = 68;
    extern __shared__ uint32_t sm[];
    uint32_t* sAh = sm;                            // [128][AP]
    uint32_t* sAl = sAh + 128 * AP;
    uint32_t* sBh = sAl + 128 * AP;                // [192][BP]: 3 gates x 64 cols
    uint32_t* sBl = sBh + 192 * BP;
    float*    sSc = reinterpret_cast<float*>(sBl + 192 * BP);  // [128][2]

    const int t    = threadIdx.x;
    const int m0   = blockIdx.x * 128;
    const int half = blockIdx.y;                   // cols half*64 .. +63 of each gate

    #pragma unroll
    for (int i = 0; i < 16; i++) {                 // stage + split hnew
        int f = t + i * 512;
        int row = f >> 6, k2 = f & 63;
        float2 v = (m0 + row < M)
                 ? reinterpret_cast<const float2*>(hnew)[(size_t)(m0 + row) * 64 + k2]
                 : make_float2(0.f, 0.f);
        uint32_t h, l;
        split2(v.x, v.y, h, l);
        sAh[row * AP + k2] = h;
        sAl[row * AP + k2] = l;
    }
    #pragma unroll
    for (int i = 0; i < 24; i++) {                 // stage 3 gate weight tiles
        int f = t + i * 512;                       // f < 12288
        int gcol = f >> 6, k2 = f & 63;
        int gate = gcol >> 6, c = gcol & 63;
        size_t src = (size_t)(gate * 128 + half * 64 + c) * 64 + k2;
        sBh[gcol * BP + k2] = WihH[src];
        sBl[gcol * BP + k2] = WihL[src];
    }
    __syncthreads();

    const int w = t >> 5, lane = t & 31;
    const int g = lane >> 2, tg = lane & 3;
    const int wm = (w & 7) * 16;
    const int wn = (w >> 3) * 32;                  // 32 cols per warp per gate

    const uint32_t aRowOff = ((wm + (lane & 15)) * AP + (lane >> 4) * 4) << 2;
    const uint32_t aH = smem_u32(sAh) + aRowOff;
    const uint32_t aL = smem_u32(sAl) + aRowOff;

    float acc[3][4][4];
    #pragma unroll
    for (int c3 = 0; c3 < 3; c3++)
        #pragma unroll
        for (int n = 0; n < 4; n++)
            #pragma unroll
            for (int j = 0; j < 4; j++) acc[c3][n][j] = 0.f;

    #pragma unroll
    for (int gate = 0; gate < 3; gate++) {
        uint32_t bH[2], bL[2];
        #pragma unroll
        for (int np = 0; np < 2; np++) {
            uint32_t cb = gate * 64 + wn + np * 16 + (lane & 7) + ((lane >> 4) << 3);
            uint32_t off = (cb * BP + ((lane >> 3) & 1) * 4) << 2;
            bH[np] = smem_u32(sBh) + off;
            bL[np] = smem_u32(sBl) + off;
        }
        #pragma unroll
        for (int kb = 0; kb < 8; kb++) {
            const uint32_t ko = kb * 32;
            uint32_t ah0, ah1, ah2, ah3, al0, al1, al2, al3;
            ldsm_x4(ah0, ah1, ah2, ah3, aH + ko);
            ldsm_x4(al0, al1, al2, al3, aL + ko);
            #pragma unroll
            for (int np = 0; np < 2; np++) {
                uint32_t bh0, bh1, bh2, bh3, bl0, bl1, bl2, bl3;
                ldsm_x4(bh0, bh1, bh2, bh3, bH[np] + ko);
                ldsm_x4(bl0, bl1, bl2, bl3, bL[np] + ko);
                mma_bf16(acc[gate][2*np],   ah0, ah1, ah2, ah3, bh0, bh1);
                mma_bf16(acc[gate][2*np],   ah0, ah1, ah2, ah3, bl0, bl1);
                mma_bf16(acc[gate][2*np],   al0, al1, al2, al3, bh0, bh1);
                mma_bf16(acc[gate][2*np+1], ah0, ah1, ah2, ah3, bh2, bh3);
                mma_bf16(acc[gate][2*np+1], ah0, ah1, ah2, ah3, bl2, bl3);
                mma_bf16(acc[gate][2*np+1], al0, al1, al2, al3, bh2, bh3);
            }
        }
    }

    // ---- GRU (h0 == 0 fast path) + partial score ----
    float p0 = 0.f, p1 = 0.f;
    #pragma unroll
    for (int n = 0; n < 4; n++) {
        #pragma unroll
        for (int jj = 0; jj < 2; jj++) {
            int cabs = half * 64 + wn + n * 8 + 2 * tg + jj;
            float wf  = W_final[cabs];
            float bir = b_ih[cabs], biz = b_ih[128 + cabs], bin = b_ih[256 + cabs];
            float bhr = b_hh[cabs], bhz = b_hh[128 + cabs], bhn = b_hh[256 + cabs];
            #pragma unroll
            for (int hrw = 0; hrw < 2; hrw++) {
                float rg = sigm(acc[0][n][hrw * 2 + jj] + bir + bhr);
                float zg = sigm(acc[1][n][hrw * 2 + jj] + biz + bhz);
                float ng = tanhf(acc[2][n][hrw * 2 + jj] + bin + rg * bhn);
                float h  = (1.f - zg) * ng;
                if (hrw == 0) p0 += h * wf; else p1 += h * wf;
            }
        }
    }
    p0 += __shfl_xor_sync(0xffffffffu, p0, 1);
    p0 += __shfl_xor_sync(0xffffffffu, p0, 2);
    p1 += __shfl_xor_sync(0xffffffffu, p1, 1);
    p1 += __shfl_xor_sync(0xffffffffu, p1, 2);
    if (tg == 0) {
        sSc[(wm + g) * 2     + (w >> 3)] = p0;
        sSc[(wm + g + 8) * 2 + (w >> 3)] = p1;
    }
    __syncthreads();
    if (t < 128 && m0 + t < M)
        atomicAdd(&out[m0 + t], sSc[t * 2] + sSc[t * 2 + 1]);
}

// ---------------------------------------------------------------------------
// k_fixup: only if h0 != 0 (never in this benchmark). Recomputes exact
// scores scalar-style and overwrites out. Early-exits when flag==0.
// ---------------------------------------------------------------------------
__global__ void k_fixup(const float* __restrict__ hnew,
                        const float* __restrict__ W_ih, const float* __restrict__ b_ih,
                        const float* __restrict__ W_hh, const float* __restrict__ b_hh,
                        const float* __restrict__ h0,   const float* __restrict__ W_final,
                        const int* __restrict__ flag, float* __restrict__ out, int M)
{
    if (*flag == 0) return;
    int warp = (blockIdx.x * blockDim.x + threadIdx.x) >> 5;
    int lane = threadIdx.x & 31;
    int nwarps = (gridDim.x * blockDim.x) >> 5;
    for (int n = warp; n < M; n += nwarps) {
        float acc = 0.f;
        for (int m = 0; m < 4; m++) {
            int j = lane + m * 32;
            float gr = b_ih[j], gz = b_ih[128 + j], gn = b_ih[256 + j];
            float hr = b_hh[j], hz = b_hh[128 + j], hn = b_hh[256 + j];
            for (int k = 0; k < 128; k++) {
                float hv  = hnew[(size_t)n * 128 + k];
                float h0v = h0[(size_t)n * 128 + k];
                gr += W_ih[(size_t)j * 128 + k] * hv;
                gz += W_ih[(size_t)(128 + j) * 128 + k] * hv;
                gn += W_ih[(size_t)(256 + j) * 128 + k] * hv;
                hr += W_hh[(size_t)j * 128 + k] * h0v;
                hz += W_hh[(size_t)(128 + j) * 128 + k] * h0v;
                hn += W_hh[(size_t)(256 + j) * 128 + k] * h0v;
            }
            float rg = sigm(gr + hr), zg = sigm(gz + hz);
            float ng = tanhf(gn + rg * hn);
            float h  = (1.f - zg) * ng + zg * h0[(size_t)n * 128 + j];
            acc += h * W_final[j];
        }
        #pragma unroll
        for (int off = 16; off; off >>= 1) acc += __shfl_xor_sync(0xffffffffu, acc, off);
        if (lane == 0) out[n] = acc;
    }
}

__global__ void k_flagreset(int* flag) { *flag = 0; }

// ---------------------------------------------------------------------------
// Launch. 7 launches; #4 = k_gemm2<128> (ncu capture slot).
// ---------------------------------------------------------------------------
extern "C" void kernel_launch(void* const* d_in, const int* in_sizes, int n_in,
                              void* d_out, int out_size)
{
    const float* hidden  = (const float*)d_in[0];
    const float* rel_emb = (const float*)d_in[1];
    const float* Ws      = (const float*)d_in[2];
    const float* Wr      = (const float*)d_in[3];
    const float* Wqr     = (const float*)d_in[4];
    const float* b_qr    = (const float*)d_in[5];
    const float* w_alpha = (const float*)d_in[6];
    const float* b_alpha = (const float*)d_in[7];
    const float* W_h     = (const float*)d_in[8];
    const float* W_ih    = (const float*)d_in[9];
    const float* W_hh    = (const float*)d_in[10];
    const float* b_ih    = (const float*)d_in[11];
    const float* b_hh    = (const float*)d_in[12];
    const float* W_final = (const float*)d_in[13];
    const float* h0      = (const float*)d_in[14];
    const int*   sub     = (const int*)d_in[15];
    const int*   rel     = (const int*)d_in[16];
    const int*   obj     = (const int*)d_in[17];
    const int*   ebatch  = (const int*)d_in[18];
    const int*   q_rel   = (const int*)d_in[19];
    float*       out     = (float*)d_out;

    const int Nn = in_sizes[0] / 128;
    const int Rv = in_sizes[1] / 128;
    const int Ev = in_sizes[15];
    const int Bv = in_sizes[19];

    float *pXs, *pAgg, *pHnew, *pPR, *pPQb;
    uint32_t *pWsH, *pWsL, *pWhH, *pWhL, *pWihH, *pWihL;
    int* pFlag;
    cudaGetSymbolAddress((void**)&pXs,   g_Xs);
    cudaGetSymbolAddress((void**)&pAgg,  g_agg);
    cudaGetSymbolAddress((void**)&pHnew, g_hnew);
    cudaGetSymbolAddress((void**)&pPR,   g_PR);
    cudaGetSymbolAddress((void**)&pPQb,  g_PQb);
    cudaGetSymbolAddress((void**)&pWsH,  g_WsH);
    cudaGetSymbolAddress((void**)&pWsL,  g_WsL);
    cudaGetSymbolAddress((void**)&pWhH,  g_WhH);
    cudaGetSymbolAddress((void**)&pWhL,  g_WhL);
    cudaGetSymbolAddress((void**)&pWihH, g_WihH);
    cudaGetSymbolAddress((void**)&pWihL, g_WihL);
    cudaGetSymbolAddress((void**)&pFlag, g_h0nz);

    // dynamic smem sizes (AP=BP=68)
    const int SMX = (128 * 68 * 2 + 64 * 68 * 2)  * (int)sizeof(uint32_t);           // 104 KB
    const int SMW = (128 * 68 * 2 + 128 * 68 * 2) * (int)sizeof(uint32_t);           // 139 KB
    const int SMG = (128 * 68 * 2 + 192 * 68 * 2) * (int)sizeof(uint32_t) + 1024;    // 175 KB
    cudaFuncSetAttribute(k_gemm2<64,  false>, cudaFuncAttributeMaxDynamicSharedMemorySize, SMX);
    cudaFuncSetAttribute(k_gemm2<128, true >, cudaFuncAttributeMaxDynamicSharedMemorySize, SMW);
    cudaFuncSetAttribute(k_wihgru,            cudaFuncAttributeMaxDynamicSharedMemorySize, SMG);

    const int mt128 = (Nn + 127) / 128;
    const int prepBlocks = 144 + (Rv + Bv + 3) / 4;

    // 1) setup + zero + scan (one launch)
    k_setupzero<<<prepBlocks + 2048, 256>>>(Ws, W_h, W_ih, Wr, Wqr, rel_emb,
                                            b_qr, q_rel,
                                            pWsH, pWsL, pWhH, pWhL, pWihH, pWihL,
                                            pPR, pPQb, pAgg, h0, Nn * 32,
                                            out, out_size, pFlag, Rv, Bv, prepBlocks);

    // 2) Xs = hidden @ Ws^T   [N,64]
    k_gemm2<64, false><<<mt128, 512, SMX>>>(hidden, pWsH, pWsL, pXs, Nn, 64);

    // 3) edge message passing + segment sum
    k_edge<<<(Ev + 7) / 8, 256>>>(hidden, rel_emb, w_alpha, b_alpha,
                                  sub, rel, obj, ebatch, pXs, pPR, pPQb, pAgg, Ev);

    // 4) h_new = relu(agg @ W_h^T)   [N,128]   <-- ncu capture slot
    k_gemm2<128, true><<<mt128, 512, SMW>>>(pAgg, pWhH, pWhL, pHnew, Nn, 128);

    // 5) fused W_ih GEMM + GRU + score
    k_wihgru<<<dim3(mt128, 2), 512, SMG>>>(pHnew, pWihH, pWihL, b_ih, b_hh,
                                           W_final, out, Nn);

    // 6) h0 != 0 fallback (no-op when flag == 0)
    k_fixup<<<1024, 256>>>(pHnew, W_ih, b_ih, W_hh, b_hh, h0, W_final,
                           pFlag, out, Nn);

    // 7) reset flag for next replay
    k_flagreset<<<1, 1>>>(pFlag);
}

// round 7
// speedup vs baseline: 1.4314x; 1.0328x over previous
#include <cuda_runtime.h>
#include <cuda_bf16.h>
#include <cstdint>
#include <cstddef>

// ---------------------------------------------------------------------------
// Fixed shapes: D=128 (K2=64 bf16 pairs), A=64
// ---------------------------------------------------------------------------
static constexpr size_t MAXN = 200000;
static constexpr size_t MAXB = 256;

// Scratch (device globals; no runtime allocation allowed)
__device__ float    g_Xs  [MAXN * 64];     // hidden @ Ws^T
__device__ float    g_agg [MAXN * 128];    // segment sum
__device__ float    g_hnew[MAXN * 128];    // relu(agg @ W_h^T)
__device__ float    g_PR  [128 * 64];      // rel_emb @ Wr^T   (R<=128)
__device__ float    g_PQb [MAXB * 64];     // rel_emb[q_rel[b]] @ Wqr^T + b_qr
// bf16-split weights, c-major pairs: entry [c][k2] = {W[c][2k2], W[c][2k2+1]}
__device__ uint32_t g_WsH [64 * 64],  g_WsL [64 * 64];
__device__ uint32_t g_WhH [128 * 64], g_WhL [128 * 64];
__device__ uint32_t g_WihH[384 * 64], g_WihL[384 * 64];
__device__ int      g_h0nz;                // zero-initialized; reset by k_flagreset

// ---------------------------------------------------------------------------
// Helpers
// ---------------------------------------------------------------------------
__device__ __forceinline__ uint32_t pack_bf2(__nv_bfloat16 a, __nv_bfloat16 b)
{
    __nv_bfloat162 h; h.x = a; h.y = b;
    return *reinterpret_cast<uint32_t*>(&h);
}

__device__ __forceinline__ void split2(float x, float y, uint32_t& hi, uint32_t& lo)
{
    __nv_bfloat16 hx = __float2bfloat16_rn(x), hy = __float2bfloat16_rn(y);
    float rx = x - __bfloat162float(hx);
    float ry = y - __bfloat162float(hy);
    hi = pack_bf2(hx, hy);
    lo = pack_bf2(__float2bfloat16_rn(rx), __float2bfloat16_rn(ry));
}

__device__ __forceinline__ void mma_bf16(float* c, uint32_t a0, uint32_t a1,
                                         uint32_t a2, uint32_t a3,
                                         uint32_t b0, uint32_t b1)
{
    asm volatile(
        "mma.sync.aligned.m16n8k16.row.col.f32.bf16.bf16.f32 "
        "{%0,%1,%2,%3}, {%4,%5,%6,%7}, {%8,%9}, {%0,%1,%2,%3};\n"
        : "+f"(c[0]), "+f"(c[1]), "+f"(c[2]), "+f"(c[3])
        : "r"(a0), "r"(a1), "r"(a2), "r"(a3), "r"(b0), "r"(b1));
}

__device__ __forceinline__ void ldsm_x4(uint32_t& r0, uint32_t& r1, uint32_t& r2,
                                        uint32_t& r3, uint32_t addr)
{
    asm volatile("ldmatrix.sync.aligned.m8n8.x4.shared.b16 {%0,%1,%2,%3}, [%4];"
                 : "=r"(r0), "=r"(r1), "=r"(r2), "=r"(r3) : "r"(addr));
}

__device__ __forceinline__ uint32_t smem_u32(const void* p)
{
    uint32_t a;
    asm("{ .reg .u64 t; cvta.to.shared.u64 t, %1; cvt.u32.u64 %0, t; }"
        : "=r"(a) : "l"(p));
    return a;
}

__device__ __forceinline__ float sigm(float x) { return 1.f / (1.f + __expf(-x)); }

// ---------------------------------------------------------------------------
// k_setupzero: weight splits + PR/PQb + agg/out zero + h0 scan, one launch.
// ---------------------------------------------------------------------------
__global__ void k_setupzero(
    const float* __restrict__ Ws, const float* __restrict__ W_h,
    const float* __restrict__ W_ih,
    const float* __restrict__ Wr, const float* __restrict__ Wqr,
    const float* __restrict__ rel_emb,
    const float* __restrict__ b_qr, const int* __restrict__ q_rel,
    uint32_t* __restrict__ WsH, uint32_t* __restrict__ WsL,
    uint32_t* __restrict__ WhH, uint32_t* __restrict__ WhL,
    uint32_t* __restrict__ WihH, uint32_t* __restrict__ WihL,
    float* __restrict__ PR, float* __restrict__ PQb,
    float* __restrict__ agg, const float* __restrict__ h0, int nquads,
    float* __restrict__ outbuf, int nout,
    int* __restrict__ flag, int Rv, int Bv, int prepBlocks)
{
    const int blk = blockIdx.x, t = threadIdx.x;

    if (blk < 144) {                               // 36864 split elems
        int gid = blk * 256 + t;
        const float* W; uint32_t *H, *L; int idx;
        if (gid < 4096)       { W = Ws;   H = WsH;  L = WsL;  idx = gid; }
        else if (gid < 12288) { W = W_h;  H = WhH;  L = WhL;  idx = gid - 4096; }
        else                  { W = W_ih; H = WihH; L = WihL; idx = gid - 12288; }
        int c = idx >> 6, k2 = idx & 63;
        uint32_t h, l;
        split2(W[(size_t)c * 128 + 2 * k2], W[(size_t)c * 128 + 2 * k2 + 1], h, l);
        H[idx] = h;                                // c-major: [c][64]
        L[idx] = l;
    } else if (blk < prepBlocks) {                 // PR / PQb rows
        int rid = (blk - 144) * 4 + (t >> 6);
        int a = t & 63;
        if (rid < Rv + Bv) {
            const float* Wrow; const float* emb; float* dst; float bias;
            if (rid < Rv) { Wrow = Wr;  emb = rel_emb + (size_t)rid * 128;
                            dst = PR + (size_t)rid * 64;  bias = 0.f; }
            else          { int b = rid - Rv; int r = q_rel[b];
                            Wrow = Wqr; emb = rel_emb + (size_t)r * 128;
                            dst = PQb + (size_t)b * 64;   bias = b_qr[a]; }
            float acc = bias;
            const float* wr = Wrow + (size_t)a * 128;
            #pragma unroll 8
            for (int k = 0; k < 128; k++) acc += emb[k] * wr[k];
            dst[a] = acc;
        }
    } else {                                       // zero + scan
        int zb = gridDim.x - prepBlocks;
        int i = (blk - prepBlocks) * 256 + t;
        int stride = zb * 256;
        bool nz = false;
        float4 z = make_float4(0.f, 0.f, 0.f, 0.f);
        for (int j = i; j < nquads; j += stride) {
            reinterpret_cast<float4*>(agg)[j] = z;
            float4 v = reinterpret_cast<const float4*>(h0)[j];
            nz |= (v.x != 0.f) | (v.y != 0.f) | (v.z != 0.f) | (v.w != 0.f);
        }
        for (int j = i; j < nout; j += stride) outbuf[j] = 0.f;
        if (nz) atomicOr(flag, 1);
    }
}

// ---------------------------------------------------------------------------
// BM=64 tensor-core GEMM (3-term bf16 split), 256 threads / 8 warps,
// LDSM fragment loads. 2-3 CTAs/SM (smem 69.6-104.4 KB).
// Warps: (w&3) -> 16-row tile, (w>>2) -> BN/2 columns.
// ---------------------------------------------------------------------------
template<int BN, bool RELU>
__global__ void __launch_bounds__(256, 2) k_gemm3(
    const float* __restrict__ A, const uint32_t* __restrict__ Bhi,
    const uint32_t* __restrict__ Blo, float* __restrict__ C,
    int M, int ldc)
{
    constexpr int AP = 68, BP = 68;
    constexpr int NPAIR = BN / 32;                 // ldmatrix.x4 B loads per buf
    extern __shared__ uint32_t sm[];
    uint32_t* sAh = sm;                            // [64][AP]
    uint32_t* sAl = sAh + 64 * AP;
    uint32_t* sBh = sAl + 64 * AP;                 // [BN][BP]
    uint32_t* sBl = sBh + BN * BP;

    const int t  = threadIdx.x;
    const int m0 = blockIdx.x * 64;

    #pragma unroll
    for (int i = 0; i < 16; i++) {                 // stage + split A (4096 pairs)
        int f = t + i * 256;
        int row = f >> 6, k2 = f & 63;
        float2 v = (m0 + row < M)
                 ? reinterpret_cast<const float2*>(A)[(size_t)(m0 + row) * 64 + k2]
                 : make_float2(0.f, 0.f);
        uint32_t h, l;
        split2(v.x, v.y, h, l);
        sAh[row * AP + k2] = h;
        sAl[row * AP + k2] = l;
    }
    #pragma unroll
    for (int i = 0; i < (BN * 64) / 256; i++) {    // stage B (straight copy)
        int f = t + i * 256;
        sBh[(f >> 6) * BP + (f & 63)] = Bhi[f];
        sBl[(f >> 6) * BP + (f & 63)] = Blo[f];
    }
    __syncthreads();

    const int w = t >> 5, lane = t & 31;
    const int g = lane >> 2, tg = lane & 3;
    const int wm = (w & 3) * 16;
    const int wn = (w >> 2) * (BN / 2);

    const uint32_t aRowOff = ((wm + (lane & 15)) * AP + (lane >> 4) * 4) << 2;
    const uint32_t aH = smem_u32(sAh) + aRowOff;
    const uint32_t aL = smem_u32(sAl) + aRowOff;
    uint32_t bH[NPAIR], bL[NPAIR];
    #pragma unroll
    for (int np = 0; np < NPAIR; np++) {
        uint32_t cb = wn + np * 16 + (lane & 7) + ((lane >> 4) << 3);
        uint32_t off = (cb * BP + ((lane >> 3) & 1) * 4) << 2;
        bH[np] = smem_u32(sBh) + off;
        bL[np] = smem_u32(sBl) + off;
    }

    float acc[BN / 16][4];
    #pragma unroll
    for (int n = 0; n < BN / 16; n++)
        #pragma unroll
        for (int j = 0; j < 4; j++) acc[n][j] = 0.f;

    #pragma unroll
    for (int kb = 0; kb < 8; kb++) {
        const uint32_t ko = kb * 32;
        uint32_t ah0, ah1, ah2, ah3, al0, al1, al2, al3;
        ldsm_x4(ah0, ah1, ah2, ah3, aH + ko);
        ldsm_x4(al0, al1, al2, al3, aL + ko);
        #pragma unroll
        for (int np = 0; np < NPAIR; np++) {
            uint32_t bh0, bh1, bh2, bh3, bl0, bl1, bl2, bl3;
            ldsm_x4(bh0, bh1, bh2, bh3, bH[np] + ko);
            ldsm_x4(bl0, bl1, bl2, bl3, bL[np] + ko);
            mma_bf16(acc[2*np],   ah0, ah1, ah2, ah3, bh0, bh1);
            mma_bf16(acc[2*np],   ah0, ah1, ah2, ah3, bl0, bl1);
            mma_bf16(acc[2*np],   al0, al1, al2, al3, bh0, bh1);
            mma_bf16(acc[2*np+1], ah0, ah1, ah2, ah3, bh2, bh3);
            mma_bf16(acc[2*np+1], ah0, ah1, ah2, ah3, bl2, bl3);
            mma_bf16(acc[2*np+1], al0, al1, al2, al3, bh2, bh3);
        }
    }

    const int row = m0 + wm + g;
    #pragma unroll
    for (int n = 0; n < BN / 16; n++) {
        int cabs = wn + n * 8 + 2 * tg;
        float v0 = acc[n][0], v1 = acc[n][1], v2 = acc[n][2], v3 = acc[n][3];
        if (RELU) {
            v0 = fmaxf(v0, 0.f); v1 = fmaxf(v1, 0.f);
            v2 = fmaxf(v2, 0.f); v3 = fmaxf(v3, 0.f);
        }
        if (row < M)
            *reinterpret_cast<float2*>(&C[(size_t)row * ldc + cabs]) = make_float2(v0, v1);
        if (row + 8 < M)
            *reinterpret_cast<float2*>(&C[(size_t)(row + 8) * ldc + cabs]) = make_float2(v2, v3);
    }
}

// ---------------------------------------------------------------------------
// Edge kernel: one warp per edge
// ---------------------------------------------------------------------------
__global__ void k_edge(const float* __restrict__ hidden, const float* __restrict__ rel_emb,
                       const float* __restrict__ w_alpha, const float* __restrict__ b_alpha,
                       const int* __restrict__ sub, const int* __restrict__ rel,
                       const int* __restrict__ obj, const int* __restrict__ ebatch,
                       const float* __restrict__ Xs, const float* __restrict__ PR,
                       const float* __restrict__ PQb, float* __restrict__ agg, int E)
{
    int warp = (blockIdx.x * blockDim.x + threadIdx.x) >> 5;
    int lane = threadIdx.x & 31;
    if (warp >= E) return;
    int s = sub[warp], r = rel[warp], o = obj[warp], b = ebatch[warp];

    float att0 = Xs[(size_t)s * 64 + lane]      + PR[r * 64 + lane]      + PQb[b * 64 + lane];
    float att1 = Xs[(size_t)s * 64 + lane + 32] + PR[r * 64 + lane + 32] + PQb[b * 64 + lane + 32];
    att0 = fmaxf(att0, 0.f);
    att1 = fmaxf(att1, 0.f);
    float p = att0 * w_alpha[lane] + att1 * w_alpha[lane + 32];
    #pragma unroll
    for (int off = 16; off; off >>= 1) p += __shfl_xor_sync(0xffffffffu, p, off);
    float alpha = 1.f / (1.f + __expf(-(p + b_alpha[0])));

    float4 h  = reinterpret_cast<const float4*>(hidden  + (size_t)s * 128)[lane];
    float4 rr = reinterpret_cast<const float4*>(rel_emb + (size_t)r * 128)[lane];
    float4 m  = make_float4(alpha * (h.x + rr.x), alpha * (h.y + rr.y),
                            alpha * (h.z + rr.z), alpha * (h.w + rr.w));
    atomicAdd(reinterpret_cast<float4*>(agg + (size_t)o * 128) + lane, m);
}

// ---------------------------------------------------------------------------
// Fused W_ih GEMM + GRU + score (h0==0 fast path). BM=64, 256 threads,
// grid (mt64, 4): blockIdx.y = 32-column quarter of each gate. All 3 gate
// tiles staged up front; acc 24 regs; 87.6KB smem -> 2 CTAs/SM.
// ---------------------------------------------------------------------------
__global__ void __launch_bounds__(256, 2) k_wihgru(
    const float* __restrict__ hnew,
    const uint32_t* __restrict__ WihH, const uint32_t* __restrict__ WihL,
    const float* __restrict__ b_ih, const float* __restrict__ b_hh,
    const float* __restrict__ W_final, float* __restrict__ out, int M)
{
    constexpr int AP = 68, BP = 68;
    extern __shared__ uint32_t sm[];
    uint32_t* sAh = sm;                            // [64][AP]
    uint32_t* sAl = sAh + 64 * AP;
    uint32_t* sBh = sAl + 64 * AP;                 // [96][BP]: 3 gates x 32 cols
    uint32_t* sBl = sBh + 96 * BP;
    float*    sSc = reinterpret_cast<float*>(sBl + 96 * BP);   // [64][2]

    const int t  = threadIdx.x;
    const int m0 = blockIdx.x * 64;
    const int q  = blockIdx.y;                     // cols q*32 .. +31 of each gate

    #pragma unroll
    for (int i = 0; i < 16; i++) {                 // stage + split hnew
        int f = t + i * 256;
        int row = f >> 6, k2 = f & 63;
        float2 v = (m0 + row < M)
                 ? reinterpret_cast<const float2*>(hnew)[(size_t)(m0 + row) * 64 + k2]
                 : make_float2(0.f, 0.f);
        uint32_t h, l;
        split2(v.x, v.y, h, l);
        sAh[row * AP + k2] = h;
        sAl[row * AP + k2] = l;
    }
    #pragma unroll
    for (int i = 0; i < 24; i++) {                 // stage 3 gate quarter-tiles
        int f = t + i * 256;                       // f < 6144
        int gcol = f >> 6, k2 = f & 63;
        int gate = gcol >> 5, c = gcol & 31;
        size_t src = (size_t)(gate * 128 + q * 32 + c) * 64 + k2;
        sBh[gcol * BP + k2] = WihH[src];
        sBl[gcol * BP + k2] = WihL[src];
    }
    __syncthreads();

    const int w = t >> 5, lane = t & 31;
    const int g = lane >> 2, tg = lane & 3;
    const int wm = (w & 3) * 16;
    const int wnc = (w >> 2) * 16;                 // 16 cols per warp per gate

    const uint32_t aRowOff = ((wm + (lane & 15)) * AP + (lane >> 4) * 4) << 2;
    const uint32_t aH = smem_u32(sAh) + aRowOff;
    const uint32_t aL = smem_u32(sAl) + aRowOff;
    uint32_t bH[3], bL[3];
    #pragma unroll
    for (int gate = 0; gate < 3; gate++) {
        uint32_t cb = gate * 32 + wnc + (lane & 7) + ((lane >> 4) << 3);
        uint32_t off = (cb * BP + ((lane >> 3) & 1) * 4) << 2;
        bH[gate] = smem_u32(sBh) + off;
        bL[gate] = smem_u32(sBl) + off;
    }

    float acc[3][2][4];
    #pragma unroll
    for (int c3 = 0; c3 < 3; c3++)
        #pragma unroll
        for (int n = 0; n < 2; n++)
            #pragma unroll
            for (int j = 0; j < 4; j++) acc[c3][n][j] = 0.f;

    #pragma unroll
    for (int kb = 0; kb < 8; kb++) {
        const uint32_t ko = kb * 32;
        uint32_t ah0, ah1, ah2, ah3, al0, al1, al2, al3;
        ldsm_x4(ah0, ah1, ah2, ah3, aH + ko);
        ldsm_x4(al0, al1, al2, al3, aL + ko);
        #pragma unroll
        for (int gate = 0; gate < 3; gate++) {
            uint32_t bh0, bh1, bh2, bh3, bl0, bl1, bl2, bl3;
            ldsm_x4(bh0, bh1, bh2, bh3, bH[gate] + ko);
            ldsm_x4(bl0, bl1, bl2, bl3, bL[gate] + ko);
            mma_bf16(acc[gate][0], ah0, ah1, ah2, ah3, bh0, bh1);
            mma_bf16(acc[gate][0], ah0, ah1, ah2, ah3, bl0, bl1);
            mma_bf16(acc[gate][0], al0, al1, al2, al3, bh0, bh1);
            mma_bf16(acc[gate][1], ah0, ah1, ah2, ah3, bh2, bh3);
            mma_bf16(acc[gate][1], ah0, ah1, ah2, ah3, bl2, bl3);
            mma_bf16(acc[gate][1], al0, al1, al2, al3, bh2, bh3);
        }
    }

    // ---- GRU (h0 == 0 fast path) + partial score ----
    float p0 = 0.f, p1 = 0.f;
    #pragma unroll
    for (int n = 0; n < 2; n++) {
        #pragma unroll
        for (int jj = 0; jj < 2; jj++) {
            int cabs = q * 32 + wnc + n * 8 + 2 * tg + jj;
            float wf  = W_final[cabs];
            float bir = b_ih[cabs], biz = b_ih[128 + cabs], bin = b_ih[256 + cabs];
            float bhr = b_hh[cabs], bhz = b_hh[128 + cabs], bhn = b_hh[256 + cabs];
            #pragma unroll
            for (int hrw = 0; hrw < 2; hrw++) {
                float rg = sigm(acc[0][n][hrw * 2 + jj] + bir + bhr);
                float zg = sigm(acc[1][n][hrw * 2 + jj] + biz + bhz);
                float ng = tanhf(acc[2][n][hrw * 2 + jj] + bin + rg * bhn);
                float h  = (1.f - zg) * ng;
                if (hrw == 0) p0 += h * wf; else p1 += h * wf;
            }
        }
    }
    p0 += __shfl_xor_sync(0xffffffffu, p0, 1);
    p0 += __shfl_xor_sync(0xffffffffu, p0, 2);
    p1 += __shfl_xor_sync(0xffffffffu, p1, 1);
    p1 += __shfl_xor_sync(0xffffffffu, p1, 2);
    if (tg == 0) {
        sSc[(wm + g) * 2     + (w >> 2)] = p0;
        sSc[(wm + g + 8) * 2 + (w >> 2)] = p1;
    }
    __syncthreads();
    if (t < 64 && m0 + t < M)
        atomicAdd(&out[m0 + t], sSc[t * 2] + sSc[t * 2 + 1]);
}

// ---------------------------------------------------------------------------
// k_fixup: only if h0 != 0 (never in this benchmark). Early-exits on flag==0.
// ---------------------------------------------------------------------------
__global__ void k_fixup(const float* __restrict__ hnew,
                        const float* __restrict__ W_ih, const float* __restrict__ b_ih,
                        const float* __restrict__ W_hh, const float* __restrict__ b_hh,
                        const float* __restrict__ h0,   const float* __restrict__ W_final,
                        const int* __restrict__ flag, float* __restrict__ out, int M)
{
    if (*flag == 0) return;
    int warp = (blockIdx.x * blockDim.x + threadIdx.x) >> 5;
    int lane = threadIdx.x & 31;
    int nwarps = (gridDim.x * blockDim.x) >> 5;
    for (int n = warp; n < M; n += nwarps) {
        float acc = 0.f;
        for (int m = 0; m < 4; m++) {
            int j = lane + m * 32;
            float gr = b_ih[j], gz = b_ih[128 + j], gn = b_ih[256 + j];
            float hr = b_hh[j], hz = b_hh[128 + j], hn = b_hh[256 + j];
            for (int k = 0; k < 128; k++) {
                float hv  = hnew[(size_t)n * 128 + k];
                float h0v = h0[(size_t)n * 128 + k];
                gr += W_ih[(size_t)j * 128 + k] * hv;
                gz += W_ih[(size_t)(128 + j) * 128 + k] * hv;
                gn += W_ih[(size_t)(256 + j) * 128 + k] * hv;
                hr += W_hh[(size_t)j * 128 + k] * h0v;
                hz += W_hh[(size_t)(128 + j) * 128 + k] * h0v;
                hn += W_hh[(size_t)(256 + j) * 128 + k] * h0v;
            }
            float rg = sigm(gr + hr), zg = sigm(gz + hz);
            float ng = tanhf(gn + rg * hn);
            float h  = (1.f - zg) * ng + zg * h0[(size_t)n * 128 + j];
            acc += h * W_final[j];
        }
        #pragma unroll
        for (int off = 16; off; off >>= 1) acc += __shfl_xor_sync(0xffffffffu, acc, off);
        if (lane == 0) out[n] = acc;
    }
}

__global__ void k_flagreset(int* flag) { *flag = 0; }

// ---------------------------------------------------------------------------
// Launch. #4 = k_gemm3<128> (ncu capture slot).
// ---------------------------------------------------------------------------
extern "C" void kernel_launch(void* const* d_in, const int* in_sizes, int n_in,
                              void* d_out, int out_size)
{
    const float* hidden  = (const float*)d_in[0];
    const float* rel_emb = (const float*)d_in[1];
    const float* Ws      = (const float*)d_in[2];
    const float* Wr      = (const float*)d_in[3];
    const float* Wqr     = (const float*)d_in[4];
    const float* b_qr    = (const float*)d_in[5];
    const float* w_alpha = (const float*)d_in[6];
    const float* b_alpha = (const float*)d_in[7];
    const float* W_h     = (const float*)d_in[8];
    const float* W_ih    = (const float*)d_in[9];
    const float* W_hh    = (const float*)d_in[10];
    const float* b_ih    = (const float*)d_in[11];
    const float* b_hh    = (const float*)d_in[12];
    const float* W_final = (const float*)d_in[13];
    const float* h0      = (const float*)d_in[14];
    const int*   sub     = (const int*)d_in[15];
    const int*   rel     = (const int*)d_in[16];
    const int*   obj     = (const int*)d_in[17];
    const int*   ebatch  = (const int*)d_in[18];
    const int*   q_rel   = (const int*)d_in[19];
    float*       out     = (float*)d_out;

    const int Nn = in_sizes[0] / 128;
    const int Rv = in_sizes[1] / 128;
    const int Ev = in_sizes[15];
    const int Bv = in_sizes[19];

    float *pXs, *pAgg, *pHnew, *pPR, *pPQb;
    uint32_t *pWsH, *pWsL, *pWhH, *pWhL, *pWihH, *pWihL;
    int* pFlag;
    cudaGetSymbolAddress((void**)&pXs,   g_Xs);
    cudaGetSymbolAddress((void**)&pAgg,  g_agg);
    cudaGetSymbolAddress((void**)&pHnew, g_hnew);
    cudaGetSymbolAddress((void**)&pPR,   g_PR);
    cudaGetSymbolAddress((void**)&pPQb,  g_PQb);
    cudaGetSymbolAddress((void**)&pWsH,  g_WsH);
    cudaGetSymbolAddress((void**)&pWsL,  g_WsL);
    cudaGetSymbolAddress((void**)&pWhH,  g_WhH);
    cudaGetSymbolAddress((void**)&pWhL,  g_WhL);
    cudaGetSymbolAddress((void**)&pWihH, g_WihH);
    cudaGetSymbolAddress((void**)&pWihL, g_WihL);
    cudaGetSymbolAddress((void**)&pFlag, g_h0nz);

    // dynamic smem sizes (AP=BP=68)
    const int SMX = (64 * 68 * 2 + 64 * 68 * 2)  * (int)sizeof(uint32_t);           //  69.6 KB
    const int SMW = (64 * 68 * 2 + 128 * 68 * 2) * (int)sizeof(uint32_t);           // 104.4 KB
    const int SMG = (64 * 68 * 2 + 96 * 68 * 2)  * (int)sizeof(uint32_t) + 512;     //  87.6 KB
    cudaFuncSetAttribute(k_gemm3<64,  false>, cudaFuncAttributeMaxDynamicSharedMemorySize, SMX);
    cudaFuncSetAttribute(k_gemm3<128, true >, cudaFuncAttributeMaxDynamicSharedMemorySize, SMW);
    cudaFuncSetAttribute(k_wihgru,            cudaFuncAttributeMaxDynamicSharedMemorySize, SMG);

    const int mt64 = (Nn + 63) / 64;
    const int prepBlocks = 144 + (Rv + Bv + 3) / 4;

    // 1) setup + zero + scan (one launch)
    k_setupzero<<<prepBlocks + 2048, 256>>>(Ws, W_h, W_ih, Wr, Wqr, rel_emb,
                                            b_qr, q_rel,
                                            pWsH, pWsL, pWhH, pWhL, pWihH, pWihL,
                                            pPR, pPQb, pAgg, h0, Nn * 32,
                                            out, out_size, pFlag, Rv, Bv, prepBlocks);

    // 2) Xs = hidden @ Ws^T   [N,64]
    k_gemm3<64, false><<<mt64, 256, SMX>>>(hidden, pWsH, pWsL, pXs, Nn, 64);

    // 3) edge message passing + segment sum
    k_edge<<<(Ev + 7) / 8, 256>>>(hidden, rel_emb, w_alpha, b_alpha,
                                  sub, rel, obj, ebatch, pXs, pPR, pPQb, pAgg, Ev);

    // 4) h_new = relu(agg @ W_h^T)   [N,128]   <-- ncu capture slot
    k_gemm3<128, true><<<mt64, 256, SMW>>>(pAgg, pWhH, pWhL, pHnew, Nn, 128);

    // 5) fused W_ih GEMM + GRU + score
    k_wihgru<<<dim3(mt64, 4), 256, SMG>>>(pHnew, pWihH, pWihL, b_ih, b_hh,
                                          W_final, out, Nn);

    // 6) h0 != 0 fallback (no-op when flag == 0)
    k_fixup<<<1024, 256>>>(pHnew, W_ih, b_ih, W_hh, b_hh, h0, W_final,
                           pFlag, out, Nn);

    // 7) reset flag for next replay
    k_flagreset<<<1, 1>>>(pFlag);
}